// round 9
// baseline (speedup 1.0000x reference)
#include <cuda_runtime.h>
#include <cuda_bf16.h>
#include <cuda_fp16.h>
#include <cstdint>

// Problem constants (fixed by setup_inputs)
#define BATCH 4
#define SEQ   2048
#define EDIM  512
#define HNUM  8
#define RNUM  16
#define DDIM  64
#define TOK   (BATCH * SEQ)      // 8192 tokens
#define ERDIM (EDIM * RNUM)      // 8192 Wv rows

// K1/K4 (bf16 [hi|hi|lo] concat path, proven)
#define KBIG  1536
#define BKC   32
#define NCHUNK (KBIG / BKC)      // 48
#define ROWB  80
#define TILEB (128 * ROWB)

// K3 (fp16 2-product path)
#define K3_TM   256
#define K3_TN   128
#define K3_NCH  16               // 512 / 32
#define RX      144              // A row pitch: 64B hi + 64B lo + 16B pad
#define RB      80               // B row pitch: 64B + 16B pad
#define K3_AT   (K3_TM * RX)     // 36864
#define K3_BT   (K3_TN * RB)     // 10240
#define K3_STAGE (K3_AT + K3_BT) // 47104
#define K3_SMEM (2 * K3_STAGE)   // 94208

// Scratch (allocation-free: __device__ globals)
__device__ float g_Q[TOK * EDIM];              // scaled query projection
__device__ float g_attn[TOK * HNUM * RNUM];    // softmax over rules
__device__ float g_iw2[HNUM * RNUM * DDIM];    // 1 / rules_widths^2
__device__ __half g_A2h[(size_t)TOK   * 1024]; // value row: fp16 [hi(512)|lo(512)]
__device__ __half g_B2h[(size_t)ERDIM * 512];  // Wv row: fp16 single plane
__device__ __nv_bfloat16 g_QSbig[(size_t)TOK * KBIG]; // query  split [hi|hi|lo]
__device__ __nv_bfloat16 g_WqB[(size_t)EDIM  * KBIG]; // Wq     split [hi|lo|hi]
__device__ __nv_bfloat16 g_WoB[(size_t)EDIM  * KBIG]; // Wo     split [hi|lo|hi]
__device__ __nv_bfloat16 g_Fbig[(size_t)TOK  * KBIG]; // F      split [hi|hi|lo], (b,h,s,d) rows

// ---------------------------------------------------------------------------
// Portable PTX helpers (sm_80+)
// ---------------------------------------------------------------------------
__device__ __forceinline__ uint32_t smem_u32(const void* p) {
    uint32_t a;
    asm("{ .reg .u64 t; cvta.to.shared.u64 t, %1; cvt.u32.u64 %0, t; }"
        : "=r"(a) : "l"(p));
    return a;
}
__device__ __forceinline__ void cp_async16(uint32_t dst, const void* src) {
    asm volatile("cp.async.cg.shared.global [%0], [%1], 16;"
                 :: "r"(dst), "l"(src) : "memory");
}
__device__ __forceinline__ void ldmatrix_x4(uint32_t* r, uint32_t addr) {
    asm volatile("ldmatrix.sync.aligned.m8n8.x4.shared.b16 {%0,%1,%2,%3}, [%4];"
                 : "=r"(r[0]), "=r"(r[1]), "=r"(r[2]), "=r"(r[3]) : "r"(addr));
}
__device__ __forceinline__ void mma_bf16(float* c, const uint32_t* a,
                                         uint32_t b0, uint32_t b1) {
    asm volatile(
        "mma.sync.aligned.m16n8k16.row.col.f32.bf16.bf16.f32 "
        "{%0,%1,%2,%3}, {%4,%5,%6,%7}, {%8,%9}, {%0,%1,%2,%3};"
        : "+f"(c[0]), "+f"(c[1]), "+f"(c[2]), "+f"(c[3])
        : "r"(a[0]), "r"(a[1]), "r"(a[2]), "r"(a[3]), "r"(b0), "r"(b1));
}
__device__ __forceinline__ void mma_fp16(float* c, const uint32_t* a,
                                         uint32_t b0, uint32_t b1) {
    asm volatile(
        "mma.sync.aligned.m16n8k16.row.col.f32.f16.f16.f32 "
        "{%0,%1,%2,%3}, {%4,%5,%6,%7}, {%8,%9}, {%0,%1,%2,%3};"
        : "+f"(c[0]), "+f"(c[1]), "+f"(c[2]), "+f"(c[3])
        : "r"(a[0]), "r"(a[1]), "r"(a[2]), "r"(a[3]), "r"(b0), "r"(b1));
}

// ---------------------------------------------------------------------------
// Preprocessing kernels
// ---------------------------------------------------------------------------
// bf16 3-plane splits for K1/K4 (proven path)
template <int MODE>
__global__ __launch_bounds__(256) void split_kernel(
    const float* __restrict__ src, __nv_bfloat16* __restrict__ dst)
{
    size_t i = (size_t)blockIdx.x * 256 + threadIdx.x;
    int row = (int)(i >> 9);
    int k   = (int)(i & 511);
    float v = src[i];
    __nv_bfloat16 hi = __float2bfloat16(v);
    __nv_bfloat16 lo = __float2bfloat16(v - __bfloat162float(hi));
    __nv_bfloat16* d = dst + (size_t)row * KBIG;
    d[k] = hi;
    if (MODE == 0) { d[512 + k] = hi; d[1024 + k] = lo; }
    else           { d[512 + k] = lo; d[1024 + k] = hi; }
}

// fp16 hi/lo 2-plane split (value). float4 per thread, half2 writes.
__global__ __launch_bounds__(256) void split2h_kernel(
    const float* __restrict__ src, __half* __restrict__ dst)
{
    size_t i = (size_t)blockIdx.x * 256 + threadIdx.x;   // over rows * 128 float4
    int row = (int)(i >> 7);
    int k4  = (int)(i & 127) * 4;
    float4 v = ((const float4*)src)[i];
    __half h0 = __float2half_rn(v.x), h1 = __float2half_rn(v.y);
    __half h2 = __float2half_rn(v.z), h3 = __float2half_rn(v.w);
    __half l0 = __float2half_rn(v.x - __half2float(h0));
    __half l1 = __float2half_rn(v.y - __half2float(h1));
    __half l2 = __float2half_rn(v.z - __half2float(h2));
    __half l3 = __float2half_rn(v.w - __half2float(h3));
    __half* d = dst + (size_t)row * 1024;
    *(__half2*)(d + k4)           = __halves2half2(h0, h1);
    *(__half2*)(d + k4 + 2)       = __halves2half2(h2, h3);
    *(__half2*)(d + 512 + k4)     = __halves2half2(l0, l1);
    *(__half2*)(d + 512 + k4 + 2) = __halves2half2(l2, l3);
}

// plain fp32 -> fp16 convert (Wv)
__global__ __launch_bounds__(256) void convh_kernel(
    const float* __restrict__ src, __half* __restrict__ dst)
{
    size_t i = (size_t)blockIdx.x * 256 + threadIdx.x;   // over total/4 float4
    float4 v = ((const float4*)src)[i];
    __half2 a = __halves2half2(__float2half_rn(v.x), __float2half_rn(v.y));
    __half2 b = __halves2half2(__float2half_rn(v.z), __float2half_rn(v.w));
    *(__half2*)(dst + i * 4)     = a;
    *(__half2*)(dst + i * 4 + 2) = b;
}

__global__ __launch_bounds__(256) void prep_iw2_kernel(const float* __restrict__ rw)
{
    int i = blockIdx.x * 256 + threadIdx.x;
    if (i < HNUM * RNUM * DDIM) {
        float t = 1.0f / rw[i];
        g_iw2[i] = t * t;
    }
}

// ---------------------------------------------------------------------------
// K2: fuzzy rule attention. One warp per (token, head); all 32 lanes active.
// ---------------------------------------------------------------------------
__global__ __launch_bounds__(256) void attn_kernel(const float* __restrict__ rk)
{
    __shared__ float qs[EDIM];
    const int token = blockIdx.x;
    {
        const float4* src = (const float4*)(g_Q + (size_t)token * EDIM);
        float4* dst = (float4*)qs;
        if (threadIdx.x < 128) dst[threadIdx.x] = src[threadIdx.x];
    }
    __syncthreads();

    const int h    = threadIdx.x >> 5;
    const int lane = threadIdx.x & 31;

    const float qa = qs[h * DDIM + lane];
    const float qb = qs[h * DDIM + lane + 32];

    float z = 0.f;
    #pragma unroll
    for (int r = 0; r < RNUM; r++) {
        const float* rp = rk    + (size_t)(h * RNUM + r) * DDIM;
        const float* wp = g_iw2 + (size_t)(h * RNUM + r) * DDIM;
        float d0 = qa - rp[lane];
        float d1 = qb - rp[lane + 32];
        float s  = d0 * d0 * wp[lane] + d1 * d1 * wp[lane + 32];
        #pragma unroll
        for (int o = 16; o; o >>= 1) s += __shfl_xor_sync(0xffffffffu, s, o);
        if (lane == r) z = s;
    }

    if (lane < 16) {
        z *= -0.5f / DDIM;
        float m = z;
        #pragma unroll
        for (int o = 8; o; o >>= 1) m = fmaxf(m, __shfl_xor_sync(0x0000ffffu, m, o));
        float e = expf(z - m);
        float sum = e;
        #pragma unroll
        for (int o = 8; o; o >>= 1) sum += __shfl_xor_sync(0x0000ffffu, sum, o);
        g_attn[(size_t)token * (HNUM * RNUM) + h * RNUM + lane] = e / sum;
    }
}

// ---------------------------------------------------------------------------
// K1/K4: bf16 HMMA split-GEMM over K'=1536, tile 128x128, double-buffered.
// ---------------------------------------------------------------------------
__global__ __launch_bounds__(256) void hmma_gemm_bias_kernel(
    const __nv_bfloat16* __restrict__ A, const __nv_bfloat16* __restrict__ B,
    const float* __restrict__ bias, float* __restrict__ C, float scale)
{
    __shared__ __align__(16) char smem[4 * TILEB];
    const uint32_t sbase = smem_u32(smem);

    const int tid    = threadIdx.x;
    const int lane   = tid & 31;
    const int wid    = tid >> 5;
    const int warp_m = wid & 1;
    const int warp_n = wid >> 1;
    const int m0     = blockIdx.y * 128;
    const int n0     = blockIdx.x * 128;

    const int lrow = tid >> 2;
    const int lc16 = tid & 3;

    float acc[4][4][4] = {};

    auto load_chunk = [&](int c, int buf) {
        const uint32_t a_s = sbase + (uint32_t)buf * TILEB;
        const uint32_t b_s = sbase + 2u * TILEB + (uint32_t)buf * TILEB;
        #pragma unroll
        for (int t = 0; t < 2; t++) {
            const int row = lrow + t * 64;
            const uint32_t so = (uint32_t)row * ROWB + (uint32_t)lc16 * 16;
            cp_async16(a_s + so, A + (size_t)(m0 + row) * KBIG + c * BKC + lc16 * 8);
            cp_async16(b_s + so, B + (size_t)(n0 + row) * KBIG + c * BKC + lc16 * 8);
        }
        asm volatile("cp.async.commit_group;" ::: "memory");
    };

    const uint32_t lm_row = (uint32_t)(lane & 15);
    const uint32_t lm_kb  = (uint32_t)(lane >> 4) * 16;

    load_chunk(0, 0);

    for (int c = 0; c < NCHUNK; c++) {
        const int buf = c & 1;
        if (c + 1 < NCHUNK) {
            load_chunk(c + 1, buf ^ 1);
            asm volatile("cp.async.wait_group 1;" ::: "memory");
        } else {
            asm volatile("cp.async.wait_group 0;" ::: "memory");
        }
        __syncthreads();

        const uint32_t a_s = sbase + (uint32_t)buf * TILEB;
        const uint32_t b_s = sbase + 2u * TILEB + (uint32_t)buf * TILEB;

        #pragma unroll
        for (int ks = 0; ks < 2; ks++) {
            const uint32_t kb = (uint32_t)ks * 32 + lm_kb;
            uint32_t afr[4][4];
            #pragma unroll
            for (int mt = 0; mt < 4; mt++) {
                const uint32_t row = (uint32_t)(warp_m * 64 + mt * 16) + lm_row;
                ldmatrix_x4(afr[mt], a_s + row * ROWB + kb);
            }
            uint32_t bfr[2][4];
            #pragma unroll
            for (int np = 0; np < 2; np++) {
                const uint32_t row = (uint32_t)(warp_n * 32 + np * 16) + lm_row;
                ldmatrix_x4(bfr[np], b_s + row * ROWB + kb);
            }
            #pragma unroll
            for (int mt = 0; mt < 4; mt++)
                #pragma unroll
                for (int nt = 0; nt < 4; nt++)
                    mma_bf16(acc[mt][nt], afr[mt],
                             bfr[nt >> 1][nt & 1], bfr[nt >> 1][(nt & 1) + 2]);
        }
        __syncthreads();
    }

    const int q  = lane & 3;
    const int rg = lane >> 2;
    #pragma unroll
    for (int mt = 0; mt < 4; mt++) {
        #pragma unroll
        for (int half = 0; half < 2; half++) {
            const int row = m0 + warp_m * 64 + mt * 16 + rg + half * 8;
            #pragma unroll
            for (int nt = 0; nt < 4; nt++) {
                const int col = n0 + warp_n * 32 + nt * 8 + q * 2;
                float2 v;
                v.x = (acc[mt][nt][half * 2 + 0] + bias[col])     * scale;
                v.y = (acc[mt][nt][half * 2 + 1] + bias[col + 1]) * scale;
                *(float2*)(C + (size_t)row * EDIM + col) = v;
            }
        }
    }
}

// ---------------------------------------------------------------------------
// K3: fp16 2-product split-GEMM + fused fuzzy epilogue.
//   Per 32-K chunk: Ahi,Alo (256x32 fp16) and B (128x32 fp16);
//   acc += Ahi*B + Alo*B  (exact A, B rounded to fp16: rel err ~2.8e-4).
// Tile 256x128, 512 threads (warps 4x4), 2-stage cp.async, 1 sync per chunk.
// Writes g_Fbig [hi|hi|lo] bf16 in (b,h,s,d) row order.
// ---------------------------------------------------------------------------
__global__ void __launch_bounds__(512, 1) hmma_fused_v3_kernel(const float* __restrict__ bv)
{
    extern __shared__ __align__(16) char smem[];
    const uint32_t sbase = smem_u32(smem);

    const int tid    = threadIdx.x;
    const int lane   = tid & 31;
    const int wid    = tid >> 5;
    const int warp_m = wid & 3;     // 4 x 64 rows
    const int warp_n = wid >> 2;    // 4 x 32 cols
    const int m0     = blockIdx.y * K3_TM;   // token base
    const int n0     = blockIdx.x * K3_TN;   // Wv-row base

    float acc[4][4][4] = {};

    auto load_chunk = [&](int c, int buf) {
        const uint32_t s0 = sbase + (uint32_t)buf * K3_STAGE;
        #pragma unroll
        for (int i = 0; i < 4; i++) {        // A: 256 rows x (hi,lo) x 4 x 16B
            const int idx  = tid + i * 512;
            const int row  = idx >> 3;
            const int half = (idx >> 2) & 1;
            const int c16  = idx & 3;
            cp_async16(s0 + (uint32_t)row * RX + (uint32_t)half * 64 + (uint32_t)c16 * 16,
                       g_A2h + (size_t)(m0 + row) * 1024 + half * 512 + c * 32 + c16 * 8);
        }
        {                                     // B: 128 rows x 4 x 16B
            const int row = tid >> 2;
            const int c16 = tid & 3;
            cp_async16(s0 + K3_AT + (uint32_t)row * RB + (uint32_t)c16 * 16,
                       g_B2h + (size_t)(n0 + row) * 512 + c * 32 + c16 * 8);
        }
        asm volatile("cp.async.commit_group;" ::: "memory");
    };

    const uint32_t lm_row = (uint32_t)(lane & 15);
    const uint32_t lm_kb  = (uint32_t)(lane >> 4) * 16;

    load_chunk(0, 0);

    for (int c = 0; c < K3_NCH; c++) {
        asm volatile("cp.async.wait_group 0;" ::: "memory");
        __syncthreads();
        // slot (c+1)&1 was last read in chunk c-1; safe after the sync above.
        if (c + 1 < K3_NCH) load_chunk(c + 1, (c + 1) & 1);

        const uint32_t a_s = sbase + (uint32_t)(c & 1) * K3_STAGE;
        const uint32_t b_s = a_s + K3_AT;

        #pragma unroll
        for (int ks = 0; ks < 2; ks++) {
            const uint32_t kb = (uint32_t)ks * 32 + lm_kb;
            uint32_t afr[4][4];
            uint32_t bfr[2][4];
            #pragma unroll
            for (int np = 0; np < 2; np++) {          // B
                const uint32_t row = (uint32_t)(warp_n * 32 + np * 16) + lm_row;
                ldmatrix_x4(bfr[np], b_s + row * RB + kb);
            }
            #pragma unroll
            for (int mt = 0; mt < 4; mt++) {          // A hi
                const uint32_t row = (uint32_t)(warp_m * 64 + mt * 16) + lm_row;
                ldmatrix_x4(afr[mt], a_s + row * RX + kb);
            }
            #pragma unroll
            for (int mt = 0; mt < 4; mt++)            // P1: Ahi * B
                #pragma unroll
                for (int nt = 0; nt < 4; nt++)
                    mma_fp16(acc[mt][nt], afr[mt],
                             bfr[nt >> 1][nt & 1], bfr[nt >> 1][(nt & 1) + 2]);
            #pragma unroll
            for (int mt = 0; mt < 4; mt++) {          // A lo (reuse afr regs)
                const uint32_t row = (uint32_t)(warp_m * 64 + mt * 16) + lm_row;
                ldmatrix_x4(afr[mt], a_s + row * RX + kb + 64);
            }
            #pragma unroll
            for (int mt = 0; mt < 4; mt++)            // P2: Alo * B
                #pragma unroll
                for (int nt = 0; nt < 4; nt++)
                    mma_fp16(acc[mt][nt], afr[mt],
                             bfr[nt >> 1][nt & 1], bfr[nt >> 1][(nt & 1) + 2]);
        }
    }

    // -------- fused fuzzy epilogue (emits hi/lo bf16 split of F) --------
    const int q   = lane & 3;
    const int rg  = lane >> 2;
    const int hd0 = n0 >> 4;      // first feature of tile (multiple of 8)
    const int h   = hd0 >> 6;
    const int d0c = hd0 & 63;

    float bvv[2][4];
    #pragma unroll
    for (int g = 0; g < 2; g++)
        #pragma unroll
        for (int ntl = 0; ntl < 2; ntl++)
            #pragma unroll
            for (int j = 0; j < 2; j++)
                bvv[g][ntl * 2 + j] =
                    __ldg(bv + n0 + warp_n * 32 + g * 16 + ntl * 8 + q * 2 + j);

    #pragma unroll
    for (int mt = 0; mt < 4; mt++) {
        #pragma unroll
        for (int half = 0; half < 2; half++) {
            const int rowm  = warp_m * 64 + mt * 16 + rg + half * 8;
            const int token = m0 + rowm;
            const int b     = token >> 11;
            const int s     = token & 2047;
            const float* ap = g_attn + (size_t)token * (HNUM * RNUM) + h * RNUM;
            const float at0 = ap[q * 2],     at1 = ap[q * 2 + 1];
            const float at2 = ap[q * 2 + 8], at3 = ap[q * 2 + 9];

            const int frow  = (b * HNUM + h) * 256 + (s >> 3);
            const int cbase = (s & 7) * 64;

            #pragma unroll
            for (int g = 0; g < 2; g++) {
                float p = (acc[mt][g * 2 + 0][half * 2 + 0] + bvv[g][0]) * at0
                        + (acc[mt][g * 2 + 0][half * 2 + 1] + bvv[g][1]) * at1
                        + (acc[mt][g * 2 + 1][half * 2 + 0] + bvv[g][2]) * at2
                        + (acc[mt][g * 2 + 1][half * 2 + 1] + bvv[g][3]) * at3;
                p += __shfl_down_sync(0xffffffffu, p, 2);
                p += __shfl_down_sync(0xffffffffu, p, 1);
                if (q == 0) {
                    p *= 0.125f;  // D^-0.5
                    const int col = cbase + d0c + warp_n * 2 + g;
                    __nv_bfloat16 hi = __float2bfloat16(p);
                    __nv_bfloat16 lo = __float2bfloat16(p - __bfloat162float(hi));
                    __nv_bfloat16* f = g_Fbig + (size_t)frow * KBIG + col;
                    f[0]    = hi;
                    f[512]  = hi;
                    f[1024] = lo;
                }
            }
        }
    }
}

// ---------------------------------------------------------------------------
extern "C" void kernel_launch(void* const* d_in, const int* in_sizes, int n_in,
                              void* d_out, int out_size)
{
    const float* query = (const float*)d_in[0];
    // d_in[1] = key: unused by the reference computation
    const float* value = (const float*)d_in[2];
    const float* Wq    = (const float*)d_in[3];
    const float* bq    = (const float*)d_in[4];
    const float* Wv    = (const float*)d_in[5];
    const float* bv    = (const float*)d_in[6];
    const float* Wo    = (const float*)d_in[7];
    const float* bo    = (const float*)d_in[8];
    const float* rk    = (const float*)d_in[9];
    const float* rw    = (const float*)d_in[10];
    float* out = (float*)d_out;

    float* Qp = nullptr;
    __half *A2p = nullptr, *B2p = nullptr;
    __nv_bfloat16 *QSp = nullptr, *WqBp = nullptr, *WoBp = nullptr, *Fp = nullptr;
    cudaGetSymbolAddress((void**)&Qp,   g_Q);
    cudaGetSymbolAddress((void**)&A2p,  g_A2h);
    cudaGetSymbolAddress((void**)&B2p,  g_B2h);
    cudaGetSymbolAddress((void**)&QSp,  g_QSbig);
    cudaGetSymbolAddress((void**)&WqBp, g_WqB);
    cudaGetSymbolAddress((void**)&WoBp, g_WoB);
    cudaGetSymbolAddress((void**)&Fp,   g_Fbig);

    cudaFuncSetAttribute(hmma_fused_v3_kernel,
                         cudaFuncAttributeMaxDynamicSharedMemorySize, K3_SMEM);

    dim3 blk(256);

    // operand preprocessing
    split2h_kernel<<<dim3((TOK * EDIM) / 1024), blk>>>(value, A2p);     // fp16 hi/lo
    convh_kernel<<<dim3((ERDIM * EDIM) / 1024), blk>>>(Wv, B2p);        // fp16
    split_kernel<0><<<dim3((TOK  * EDIM) / 256), blk>>>(query, QSp);
    split_kernel<1><<<dim3((EDIM * EDIM) / 256), blk>>>(Wq, WqBp);
    split_kernel<1><<<dim3((EDIM * EDIM) / 256), blk>>>(Wo, WoBp);
    prep_iw2_kernel<<<dim3((HNUM * RNUM * DDIM + 255) / 256), blk>>>(rw);

    // K1: q projection (scaled) via bf16 HMMA
    hmma_gemm_bias_kernel<<<dim3(EDIM / 128, TOK / 128), blk>>>(
        QSp, WqBp, bq, Qp, 0.125f);

    // K2: fuzzy rule attention
    attn_kernel<<<dim3(TOK), blk>>>(rk);

    // K3: fused v-GEMM + rule reduction, fp16 2-product scheme
    hmma_fused_v3_kernel<<<dim3(ERDIM / K3_TN, TOK / K3_TM), dim3(512), K3_SMEM>>>(bv);

    // K4: output projection via bf16 HMMA
    hmma_gemm_bias_kernel<<<dim3(EDIM / 128, TOK / 128), blk>>>(
        Fp, WoBp, bo, out, 1.0f);
}

// round 10
// speedup vs baseline: 1.0011x; 1.0011x over previous
#include <cuda_runtime.h>
#include <cuda_bf16.h>
#include <cuda_fp16.h>
#include <cstdint>

// Problem constants (fixed by setup_inputs)
#define BATCH 4
#define SEQ   2048
#define EDIM  512
#define HNUM  8
#define RNUM  16
#define DDIM  64
#define TOK   (BATCH * SEQ)      // 8192 tokens
#define ERDIM (EDIM * RNUM)      // 8192 Wv rows

// K1/K4 (bf16 [hi|hi|lo] concat path, proven)
#define KBIG  1536
#define BKC   32
#define NCHUNK (KBIG / BKC)      // 48
#define ROWB  80
#define TILEB (128 * ROWB)

// K3 (fp16 2-product path)
#define K3_TM   256
#define K3_TN   128
#define K3_NCH  16               // 512 / 32
#define RX      144              // A row pitch: 64B hi + 64B lo + 16B pad
#define RB      80               // B row pitch: 64B + 16B pad
#define K3_AT   (K3_TM * RX)     // 36864
#define K3_BT   (K3_TN * RB)     // 10240
#define K3_STAGE (K3_AT + K3_BT) // 47104
#define K3_SMEM (2 * K3_STAGE)   // 94208

// Scratch (allocation-free: __device__ globals)
__device__ float g_Q[TOK * EDIM];              // scaled query projection
__device__ float g_attn[TOK * HNUM * RNUM];    // softmax over rules
__device__ float g_iw2[HNUM * RNUM * DDIM];    // 1 / rules_widths^2
__device__ __half g_A2h[(size_t)TOK   * 1024]; // value row: fp16 [hi(512)|lo(512)]
__device__ __half g_B2h[(size_t)ERDIM * 512];  // Wv row: fp16 single plane
__device__ __nv_bfloat16 g_QSbig[(size_t)TOK * KBIG]; // query  split [hi|hi|lo]
__device__ __nv_bfloat16 g_WqB[(size_t)EDIM  * KBIG]; // Wq     split [hi|lo|hi]
__device__ __nv_bfloat16 g_WoB[(size_t)EDIM  * KBIG]; // Wo     split [hi|lo|hi]
__device__ __nv_bfloat16 g_Fbig[(size_t)TOK  * KBIG]; // F      split [hi|hi|lo], (b,h,s,d) rows

// ---------------------------------------------------------------------------
// Portable PTX helpers (sm_80+)
// ---------------------------------------------------------------------------
__device__ __forceinline__ uint32_t smem_u32(const void* p) {
    uint32_t a;
    asm("{ .reg .u64 t; cvta.to.shared.u64 t, %1; cvt.u32.u64 %0, t; }"
        : "=r"(a) : "l"(p));
    return a;
}
__device__ __forceinline__ void cp_async16(uint32_t dst, const void* src) {
    asm volatile("cp.async.cg.shared.global [%0], [%1], 16;"
                 :: "r"(dst), "l"(src) : "memory");
}
__device__ __forceinline__ void ldmatrix_x4(uint32_t* r, uint32_t addr) {
    asm volatile("ldmatrix.sync.aligned.m8n8.x4.shared.b16 {%0,%1,%2,%3}, [%4];"
                 : "=r"(r[0]), "=r"(r[1]), "=r"(r[2]), "=r"(r[3]) : "r"(addr));
}
__device__ __forceinline__ void mma_bf16(float* c, const uint32_t* a,
                                         uint32_t b0, uint32_t b1) {
    asm volatile(
        "mma.sync.aligned.m16n8k16.row.col.f32.bf16.bf16.f32 "
        "{%0,%1,%2,%3}, {%4,%5,%6,%7}, {%8,%9}, {%0,%1,%2,%3};"
        : "+f"(c[0]), "+f"(c[1]), "+f"(c[2]), "+f"(c[3])
        : "r"(a[0]), "r"(a[1]), "r"(a[2]), "r"(a[3]), "r"(b0), "r"(b1));
}
__device__ __forceinline__ void mma_fp16(float* c, const uint32_t* a,
                                         uint32_t b0, uint32_t b1) {
    asm volatile(
        "mma.sync.aligned.m16n8k16.row.col.f32.f16.f16.f32 "
        "{%0,%1,%2,%3}, {%4,%5,%6,%7}, {%8,%9}, {%0,%1,%2,%3};"
        : "+f"(c[0]), "+f"(c[1]), "+f"(c[2]), "+f"(c[3])
        : "r"(a[0]), "r"(a[1]), "r"(a[2]), "r"(a[3]), "r"(b0), "r"(b1));
}

// ---------------------------------------------------------------------------
// Preprocessing kernels
// ---------------------------------------------------------------------------
// bf16 3-plane splits for K1/K4 (proven path)
template <int MODE>
__global__ __launch_bounds__(256) void split_kernel(
    const float* __restrict__ src, __nv_bfloat16* __restrict__ dst)
{
    size_t i = (size_t)blockIdx.x * 256 + threadIdx.x;
    int row = (int)(i >> 9);
    int k   = (int)(i & 511);
    float v = src[i];
    __nv_bfloat16 hi = __float2bfloat16(v);
    __nv_bfloat16 lo = __float2bfloat16(v - __bfloat162float(hi));
    __nv_bfloat16* d = dst + (size_t)row * KBIG;
    d[k] = hi;
    if (MODE == 0) { d[512 + k] = hi; d[1024 + k] = lo; }
    else           { d[512 + k] = lo; d[1024 + k] = hi; }
}

// fp16 hi/lo 2-plane split (value). float4 per thread, half2 writes.
__global__ __launch_bounds__(256) void split2h_kernel(
    const float* __restrict__ src, __half* __restrict__ dst)
{
    size_t i = (size_t)blockIdx.x * 256 + threadIdx.x;   // over rows * 128 float4
    int row = (int)(i >> 7);
    int k4  = (int)(i & 127) * 4;
    float4 v = ((const float4*)src)[i];
    __half h0 = __float2half_rn(v.x), h1 = __float2half_rn(v.y);
    __half h2 = __float2half_rn(v.z), h3 = __float2half_rn(v.w);
    __half l0 = __float2half_rn(v.x - __half2float(h0));
    __half l1 = __float2half_rn(v.y - __half2float(h1));
    __half l2 = __float2half_rn(v.z - __half2float(h2));
    __half l3 = __float2half_rn(v.w - __half2float(h3));
    __half* d = dst + (size_t)row * 1024;
    *(__half2*)(d + k4)           = __halves2half2(h0, h1);
    *(__half2*)(d + k4 + 2)       = __halves2half2(h2, h3);
    *(__half2*)(d + 512 + k4)     = __halves2half2(l0, l1);
    *(__half2*)(d + 512 + k4 + 2) = __halves2half2(l2, l3);
}

// plain fp32 -> fp16 convert (Wv)
__global__ __launch_bounds__(256) void convh_kernel(
    const float* __restrict__ src, __half* __restrict__ dst)
{
    size_t i = (size_t)blockIdx.x * 256 + threadIdx.x;   // over total/4 float4
    float4 v = ((const float4*)src)[i];
    __half2 a = __halves2half2(__float2half_rn(v.x), __float2half_rn(v.y));
    __half2 b = __halves2half2(__float2half_rn(v.z), __float2half_rn(v.w));
    *(__half2*)(dst + i * 4)     = a;
    *(__half2*)(dst + i * 4 + 2) = b;
}

__global__ __launch_bounds__(256) void prep_iw2_kernel(const float* __restrict__ rw)
{
    int i = blockIdx.x * 256 + threadIdx.x;
    if (i < HNUM * RNUM * DDIM) {
        float t = 1.0f / rw[i];
        g_iw2[i] = t * t;
    }
}

// ---------------------------------------------------------------------------
// K2: fuzzy rule attention. One warp per (token, head); all 32 lanes active.
// ---------------------------------------------------------------------------
__global__ __launch_bounds__(256) void attn_kernel(const float* __restrict__ rk)
{
    __shared__ float qs[EDIM];
    const int token = blockIdx.x;
    {
        const float4* src = (const float4*)(g_Q + (size_t)token * EDIM);
        float4* dst = (float4*)qs;
        if (threadIdx.x < 128) dst[threadIdx.x] = src[threadIdx.x];
    }
    __syncthreads();

    const int h    = threadIdx.x >> 5;
    const int lane = threadIdx.x & 31;

    const float qa = qs[h * DDIM + lane];
    const float qb = qs[h * DDIM + lane + 32];

    float z = 0.f;
    #pragma unroll
    for (int r = 0; r < RNUM; r++) {
        const float* rp = rk    + (size_t)(h * RNUM + r) * DDIM;
        const float* wp = g_iw2 + (size_t)(h * RNUM + r) * DDIM;
        float d0 = qa - rp[lane];
        float d1 = qb - rp[lane + 32];
        float s  = d0 * d0 * wp[lane] + d1 * d1 * wp[lane + 32];
        #pragma unroll
        for (int o = 16; o; o >>= 1) s += __shfl_xor_sync(0xffffffffu, s, o);
        if (lane == r) z = s;
    }

    if (lane < 16) {
        z *= -0.5f / DDIM;
        float m = z;
        #pragma unroll
        for (int o = 8; o; o >>= 1) m = fmaxf(m, __shfl_xor_sync(0x0000ffffu, m, o));
        float e = expf(z - m);
        float sum = e;
        #pragma unroll
        for (int o = 8; o; o >>= 1) sum += __shfl_xor_sync(0x0000ffffu, sum, o);
        g_attn[(size_t)token * (HNUM * RNUM) + h * RNUM + lane] = e / sum;
    }
}

// ---------------------------------------------------------------------------
// K1/K4: bf16 HMMA split-GEMM over K'=1536, tile 128x128, double-buffered.
// ---------------------------------------------------------------------------
__global__ __launch_bounds__(256) void hmma_gemm_bias_kernel(
    const __nv_bfloat16* __restrict__ A, const __nv_bfloat16* __restrict__ B,
    const float* __restrict__ bias, float* __restrict__ C, float scale)
{
    __shared__ __align__(16) char smem[4 * TILEB];
    const uint32_t sbase = smem_u32(smem);

    const int tid    = threadIdx.x;
    const int lane   = tid & 31;
    const int wid    = tid >> 5;
    const int warp_m = wid & 1;
    const int warp_n = wid >> 1;
    const int m0     = blockIdx.y * 128;
    const int n0     = blockIdx.x * 128;

    const int lrow = tid >> 2;
    const int lc16 = tid & 3;

    float acc[4][4][4] = {};

    auto load_chunk = [&](int c, int buf) {
        const uint32_t a_s = sbase + (uint32_t)buf * TILEB;
        const uint32_t b_s = sbase + 2u * TILEB + (uint32_t)buf * TILEB;
        #pragma unroll
        for (int t = 0; t < 2; t++) {
            const int row = lrow + t * 64;
            const uint32_t so = (uint32_t)row * ROWB + (uint32_t)lc16 * 16;
            cp_async16(a_s + so, A + (size_t)(m0 + row) * KBIG + c * BKC + lc16 * 8);
            cp_async16(b_s + so, B + (size_t)(n0 + row) * KBIG + c * BKC + lc16 * 8);
        }
        asm volatile("cp.async.commit_group;" ::: "memory");
    };

    const uint32_t lm_row = (uint32_t)(lane & 15);
    const uint32_t lm_kb  = (uint32_t)(lane >> 4) * 16;

    load_chunk(0, 0);

    for (int c = 0; c < NCHUNK; c++) {
        const int buf = c & 1;
        if (c + 1 < NCHUNK) {
            load_chunk(c + 1, buf ^ 1);
            asm volatile("cp.async.wait_group 1;" ::: "memory");
        } else {
            asm volatile("cp.async.wait_group 0;" ::: "memory");
        }
        __syncthreads();

        const uint32_t a_s = sbase + (uint32_t)buf * TILEB;
        const uint32_t b_s = sbase + 2u * TILEB + (uint32_t)buf * TILEB;

        #pragma unroll
        for (int ks = 0; ks < 2; ks++) {
            const uint32_t kb = (uint32_t)ks * 32 + lm_kb;
            uint32_t afr[4][4];
            #pragma unroll
            for (int mt = 0; mt < 4; mt++) {
                const uint32_t row = (uint32_t)(warp_m * 64 + mt * 16) + lm_row;
                ldmatrix_x4(afr[mt], a_s + row * ROWB + kb);
            }
            uint32_t bfr[2][4];
            #pragma unroll
            for (int np = 0; np < 2; np++) {
                const uint32_t row = (uint32_t)(warp_n * 32 + np * 16) + lm_row;
                ldmatrix_x4(bfr[np], b_s + row * ROWB + kb);
            }
            #pragma unroll
            for (int mt = 0; mt < 4; mt++)
                #pragma unroll
                for (int nt = 0; nt < 4; nt++)
                    mma_bf16(acc[mt][nt], afr[mt],
                             bfr[nt >> 1][nt & 1], bfr[nt >> 1][(nt & 1) + 2]);
        }
        __syncthreads();
    }

    const int q  = lane & 3;
    const int rg = lane >> 2;
    #pragma unroll
    for (int mt = 0; mt < 4; mt++) {
        #pragma unroll
        for (int half = 0; half < 2; half++) {
            const int row = m0 + warp_m * 64 + mt * 16 + rg + half * 8;
            #pragma unroll
            for (int nt = 0; nt < 4; nt++) {
                const int col = n0 + warp_n * 32 + nt * 8 + q * 2;
                float2 v;
                v.x = (acc[mt][nt][half * 2 + 0] + bias[col])     * scale;
                v.y = (acc[mt][nt][half * 2 + 1] + bias[col + 1]) * scale;
                *(float2*)(C + (size_t)row * EDIM + col) = v;
            }
        }
    }
}

// ---------------------------------------------------------------------------
// K3: fp16 2-product split-GEMM + fused fuzzy epilogue.
//   Per 32-K chunk: Ahi,Alo (256x32 fp16) and B (128x32 fp16);
//   acc += Ahi*B + Alo*B  (exact A, B rounded to fp16: rel err ~2.8e-4).
// Tile 256x128, 512 threads (warps 4x4), 2-stage cp.async, 1 sync per chunk.
// Writes g_Fbig [hi|hi|lo] bf16 in (b,h,s,d) row order.
// ---------------------------------------------------------------------------
__global__ void __launch_bounds__(512, 1) hmma_fused_v3_kernel(const float* __restrict__ bv)
{
    extern __shared__ __align__(16) char smem[];
    const uint32_t sbase = smem_u32(smem);

    const int tid    = threadIdx.x;
    const int lane   = tid & 31;
    const int wid    = tid >> 5;
    const int warp_m = wid & 3;     // 4 x 64 rows
    const int warp_n = wid >> 2;    // 4 x 32 cols
    const int m0     = blockIdx.y * K3_TM;   // token base
    const int n0     = blockIdx.x * K3_TN;   // Wv-row base

    float acc[4][4][4] = {};

    auto load_chunk = [&](int c, int buf) {
        const uint32_t s0 = sbase + (uint32_t)buf * K3_STAGE;
        #pragma unroll
        for (int i = 0; i < 4; i++) {        // A: 256 rows x (hi,lo) x 4 x 16B
            const int idx  = tid + i * 512;
            const int row  = idx >> 3;
            const int half = (idx >> 2) & 1;
            const int c16  = idx & 3;
            cp_async16(s0 + (uint32_t)row * RX + (uint32_t)half * 64 + (uint32_t)c16 * 16,
                       g_A2h + (size_t)(m0 + row) * 1024 + half * 512 + c * 32 + c16 * 8);
        }
        {                                     // B: 128 rows x 4 x 16B
            const int row = tid >> 2;
            const int c16 = tid & 3;
            cp_async16(s0 + K3_AT + (uint32_t)row * RB + (uint32_t)c16 * 16,
                       g_B2h + (size_t)(n0 + row) * 512 + c * 32 + c16 * 8);
        }
        asm volatile("cp.async.commit_group;" ::: "memory");
    };

    const uint32_t lm_row = (uint32_t)(lane & 15);
    const uint32_t lm_kb  = (uint32_t)(lane >> 4) * 16;

    load_chunk(0, 0);

    for (int c = 0; c < K3_NCH; c++) {
        asm volatile("cp.async.wait_group 0;" ::: "memory");
        __syncthreads();
        // slot (c+1)&1 was last read in chunk c-1; safe after the sync above.
        if (c + 1 < K3_NCH) load_chunk(c + 1, (c + 1) & 1);

        const uint32_t a_s = sbase + (uint32_t)(c & 1) * K3_STAGE;
        const uint32_t b_s = a_s + K3_AT;

        #pragma unroll
        for (int ks = 0; ks < 2; ks++) {
            const uint32_t kb = (uint32_t)ks * 32 + lm_kb;
            uint32_t afr[4][4];
            uint32_t bfr[2][4];
            #pragma unroll
            for (int np = 0; np < 2; np++) {          // B
                const uint32_t row = (uint32_t)(warp_n * 32 + np * 16) + lm_row;
                ldmatrix_x4(bfr[np], b_s + row * RB + kb);
            }
            #pragma unroll
            for (int mt = 0; mt < 4; mt++) {          // A hi
                const uint32_t row = (uint32_t)(warp_m * 64 + mt * 16) + lm_row;
                ldmatrix_x4(afr[mt], a_s + row * RX + kb);
            }
            #pragma unroll
            for (int mt = 0; mt < 4; mt++)            // P1: Ahi * B
                #pragma unroll
                for (int nt = 0; nt < 4; nt++)
                    mma_fp16(acc[mt][nt], afr[mt],
                             bfr[nt >> 1][nt & 1], bfr[nt >> 1][(nt & 1) + 2]);
            #pragma unroll
            for (int mt = 0; mt < 4; mt++) {          // A lo (reuse afr regs)
                const uint32_t row = (uint32_t)(warp_m * 64 + mt * 16) + lm_row;
                ldmatrix_x4(afr[mt], a_s + row * RX + kb + 64);
            }
            #pragma unroll
            for (int mt = 0; mt < 4; mt++)            // P2: Alo * B
                #pragma unroll
                for (int nt = 0; nt < 4; nt++)
                    mma_fp16(acc[mt][nt], afr[mt],
                             bfr[nt >> 1][nt & 1], bfr[nt >> 1][(nt & 1) + 2]);
        }
    }

    // -------- fused fuzzy epilogue (emits hi/lo bf16 split of F) --------
    const int q   = lane & 3;
    const int rg  = lane >> 2;
    const int hd0 = n0 >> 4;      // first feature of tile (multiple of 8)
    const int h   = hd0 >> 6;
    const int d0c = hd0 & 63;

    float bvv[2][4];
    #pragma unroll
    for (int g = 0; g < 2; g++)
        #pragma unroll
        for (int ntl = 0; ntl < 2; ntl++)
            #pragma unroll
            for (int j = 0; j < 2; j++)
                bvv[g][ntl * 2 + j] =
                    __ldg(bv + n0 + warp_n * 32 + g * 16 + ntl * 8 + q * 2 + j);

    #pragma unroll
    for (int mt = 0; mt < 4; mt++) {
        #pragma unroll
        for (int half = 0; half < 2; half++) {
            const int rowm  = warp_m * 64 + mt * 16 + rg + half * 8;
            const int token = m0 + rowm;
            const int b     = token >> 11;
            const int s     = token & 2047;
            const float* ap = g_attn + (size_t)token * (HNUM * RNUM) + h * RNUM;
            const float at0 = ap[q * 2],     at1 = ap[q * 2 + 1];
            const float at2 = ap[q * 2 + 8], at3 = ap[q * 2 + 9];

            const int frow  = (b * HNUM + h) * 256 + (s >> 3);
            const int cbase = (s & 7) * 64;

            #pragma unroll
            for (int g = 0; g < 2; g++) {
                float p = (acc[mt][g * 2 + 0][half * 2 + 0] + bvv[g][0]) * at0
                        + (acc[mt][g * 2 + 0][half * 2 + 1] + bvv[g][1]) * at1
                        + (acc[mt][g * 2 + 1][half * 2 + 0] + bvv[g][2]) * at2
                        + (acc[mt][g * 2 + 1][half * 2 + 1] + bvv[g][3]) * at3;
                p += __shfl_down_sync(0xffffffffu, p, 2);
                p += __shfl_down_sync(0xffffffffu, p, 1);
                if (q == 0) {
                    p *= 0.125f;  // D^-0.5
                    const int col = cbase + d0c + warp_n * 2 + g;
                    __nv_bfloat16 hi = __float2bfloat16(p);
                    __nv_bfloat16 lo = __float2bfloat16(p - __bfloat162float(hi));
                    __nv_bfloat16* f = g_Fbig + (size_t)frow * KBIG + col;
                    f[0]    = hi;
                    f[512]  = hi;
                    f[1024] = lo;
                }
            }
        }
    }
}

// ---------------------------------------------------------------------------
extern "C" void kernel_launch(void* const* d_in, const int* in_sizes, int n_in,
                              void* d_out, int out_size)
{
    const float* query = (const float*)d_in[0];
    // d_in[1] = key: unused by the reference computation
    const float* value = (const float*)d_in[2];
    const float* Wq    = (const float*)d_in[3];
    const float* bq    = (const float*)d_in[4];
    const float* Wv    = (const float*)d_in[5];
    const float* bv    = (const float*)d_in[6];
    const float* Wo    = (const float*)d_in[7];
    const float* bo    = (const float*)d_in[8];
    const float* rk    = (const float*)d_in[9];
    const float* rw    = (const float*)d_in[10];
    float* out = (float*)d_out;

    float* Qp = nullptr;
    __half *A2p = nullptr, *B2p = nullptr;
    __nv_bfloat16 *QSp = nullptr, *WqBp = nullptr, *WoBp = nullptr, *Fp = nullptr;
    cudaGetSymbolAddress((void**)&Qp,   g_Q);
    cudaGetSymbolAddress((void**)&A2p,  g_A2h);
    cudaGetSymbolAddress((void**)&B2p,  g_B2h);
    cudaGetSymbolAddress((void**)&QSp,  g_QSbig);
    cudaGetSymbolAddress((void**)&WqBp, g_WqB);
    cudaGetSymbolAddress((void**)&WoBp, g_WoB);
    cudaGetSymbolAddress((void**)&Fp,   g_Fbig);

    cudaFuncSetAttribute(hmma_fused_v3_kernel,
                         cudaFuncAttributeMaxDynamicSharedMemorySize, K3_SMEM);

    dim3 blk(256);

    // operand preprocessing
    split2h_kernel<<<dim3((TOK * EDIM) / 1024), blk>>>(value, A2p);     // fp16 hi/lo
    convh_kernel<<<dim3((ERDIM * EDIM) / 1024), blk>>>(Wv, B2p);        // fp16
    split_kernel<0><<<dim3((TOK  * EDIM) / 256), blk>>>(query, QSp);
    split_kernel<1><<<dim3((EDIM * EDIM) / 256), blk>>>(Wq, WqBp);
    split_kernel<1><<<dim3((EDIM * EDIM) / 256), blk>>>(Wo, WoBp);
    prep_iw2_kernel<<<dim3((HNUM * RNUM * DDIM + 255) / 256), blk>>>(rw);

    // K1: q projection (scaled) via bf16 HMMA
    hmma_gemm_bias_kernel<<<dim3(EDIM / 128, TOK / 128), blk>>>(
        QSp, WqBp, bq, Qp, 0.125f);

    // K2: fuzzy rule attention
    attn_kernel<<<dim3(TOK), blk>>>(rk);

    // K3: fused v-GEMM + rule reduction, fp16 2-product scheme
    hmma_fused_v3_kernel<<<dim3(ERDIM / K3_TN, TOK / K3_TM), dim3(512), K3_SMEM>>>(bv);

    // K4: output projection via bf16 HMMA
    hmma_gemm_bias_kernel<<<dim3(EDIM / 128, TOK / 128), blk>>>(
        Fp, WoBp, bo, out, 1.0f);
}

// round 11
// speedup vs baseline: 2.0672x; 2.0649x over previous
#include <cuda_runtime.h>
#include <cuda_fp16.h>
#include <cstdint>

// Problem constants (fixed by setup_inputs)
#define BATCH 4
#define SEQ   2048
#define EDIM  512
#define HNUM  8
#define RNUM  16
#define DDIM  64
#define TOK   (BATCH * SEQ)      // 8192 tokens
#define ERDIM (EDIM * RNUM)      // 8192 Wv rows

// K1/K4 (fp16 single-product, K=512)
#define NCH16 16                 // 512 / 32
#define ROWB  80                 // 64B data + 16B pad
#define TILEB (128 * ROWB)       // 10240

// K3 (fp16 single-product, K=512, chunks of 64)
#define K3_TM   256
#define K3_TN   128
#define K3_NCH  8                // 512 / 64
#define RX      144              // 128B data + 16B pad
#define K3_AT   (K3_TM * RX)     // 36864
#define K3_BT   (K3_TN * RX)     // 18432
#define K3_STAGE (K3_AT + K3_BT) // 55296
#define K3_SMEM (2 * K3_STAGE)   // 110592

// Scratch (allocation-free: __device__ globals)
__device__ float g_Q[TOK * EDIM];              // scaled query projection (fp32)
__device__ float g_attn[TOK * HNUM * RNUM];    // softmax over rules
__device__ float g_iw2[HNUM * RNUM * DDIM];    // 1 / rules_widths^2
__device__ __half g_Vh[(size_t)TOK   * EDIM];  // value  fp16
__device__ __half g_Wvh[(size_t)ERDIM * EDIM]; // Wv     fp16
__device__ __half g_Qh[(size_t)TOK   * EDIM];  // query  fp16
__device__ __half g_Wqh[(size_t)EDIM * EDIM];  // Wq     fp16
__device__ __half g_Woh[(size_t)EDIM * EDIM];  // Wo     fp16
__device__ __half g_Fh[(size_t)TOK   * EDIM];  // F fp16, (b,h,s,d) row order

// ---------------------------------------------------------------------------
// Portable PTX helpers (sm_80+)
// ---------------------------------------------------------------------------
__device__ __forceinline__ uint32_t smem_u32(const void* p) {
    uint32_t a;
    asm("{ .reg .u64 t; cvta.to.shared.u64 t, %1; cvt.u32.u64 %0, t; }"
        : "=r"(a) : "l"(p));
    return a;
}
__device__ __forceinline__ void cp_async16(uint32_t dst, const void* src) {
    asm volatile("cp.async.cg.shared.global [%0], [%1], 16;"
                 :: "r"(dst), "l"(src) : "memory");
}
__device__ __forceinline__ void ldmatrix_x4(uint32_t* r, uint32_t addr) {
    asm volatile("ldmatrix.sync.aligned.m8n8.x4.shared.b16 {%0,%1,%2,%3}, [%4];"
                 : "=r"(r[0]), "=r"(r[1]), "=r"(r[2]), "=r"(r[3]) : "r"(addr));
}
__device__ __forceinline__ void mma_fp16(float* c, const uint32_t* a,
                                         uint32_t b0, uint32_t b1) {
    asm volatile(
        "mma.sync.aligned.m16n8k16.row.col.f32.f16.f16.f32 "
        "{%0,%1,%2,%3}, {%4,%5,%6,%7}, {%8,%9}, {%0,%1,%2,%3};"
        : "+f"(c[0]), "+f"(c[1]), "+f"(c[2]), "+f"(c[3])
        : "r"(a[0]), "r"(a[1]), "r"(a[2]), "r"(a[3]), "r"(b0), "r"(b1));
}

// ---------------------------------------------------------------------------
// fp32 -> fp16 convert (float4 per thread)
// ---------------------------------------------------------------------------
__global__ __launch_bounds__(256) void convh_kernel(
    const float* __restrict__ src, __half* __restrict__ dst)
{
    size_t i = (size_t)blockIdx.x * 256 + threadIdx.x;
    float4 v = ((const float4*)src)[i];
    __half2 a = __halves2half2(__float2half_rn(v.x), __float2half_rn(v.y));
    __half2 b = __halves2half2(__float2half_rn(v.z), __float2half_rn(v.w));
    *(__half2*)(dst + i * 4)     = a;
    *(__half2*)(dst + i * 4 + 2) = b;
}

__global__ __launch_bounds__(256) void prep_iw2_kernel(const float* __restrict__ rw)
{
    int i = blockIdx.x * 256 + threadIdx.x;
    if (i < HNUM * RNUM * DDIM) {
        float t = 1.0f / rw[i];
        g_iw2[i] = t * t;
    }
}

// ---------------------------------------------------------------------------
// K2: fuzzy rule attention. One warp per (token, head); all 32 lanes active.
// ---------------------------------------------------------------------------
__global__ __launch_bounds__(256) void attn_kernel(const float* __restrict__ rk)
{
    __shared__ float qs[EDIM];
    const int token = blockIdx.x;
    {
        const float4* src = (const float4*)(g_Q + (size_t)token * EDIM);
        float4* dst = (float4*)qs;
        if (threadIdx.x < 128) dst[threadIdx.x] = src[threadIdx.x];
    }
    __syncthreads();

    const int h    = threadIdx.x >> 5;
    const int lane = threadIdx.x & 31;

    const float qa = qs[h * DDIM + lane];
    const float qb = qs[h * DDIM + lane + 32];

    float z = 0.f;
    #pragma unroll
    for (int r = 0; r < RNUM; r++) {
        const float* rp = rk    + (size_t)(h * RNUM + r) * DDIM;
        const float* wp = g_iw2 + (size_t)(h * RNUM + r) * DDIM;
        float d0 = qa - rp[lane];
        float d1 = qb - rp[lane + 32];
        float s  = d0 * d0 * wp[lane] + d1 * d1 * wp[lane + 32];
        #pragma unroll
        for (int o = 16; o; o >>= 1) s += __shfl_xor_sync(0xffffffffu, s, o);
        if (lane == r) z = s;
    }

    if (lane < 16) {
        z *= -0.5f / DDIM;
        float m = z;
        #pragma unroll
        for (int o = 8; o; o >>= 1) m = fmaxf(m, __shfl_xor_sync(0x0000ffffu, m, o));
        float e = expf(z - m);
        float sum = e;
        #pragma unroll
        for (int o = 8; o; o >>= 1) sum += __shfl_xor_sync(0x0000ffffu, sum, o);
        g_attn[(size_t)token * (HNUM * RNUM) + h * RNUM + lane] = e / sum;
    }
}

// ---------------------------------------------------------------------------
// K1/K4: plain fp16 HMMA GEMM, K=512, tile 128x128, double-buffered.
//   C[m,n] = (A[m,:] . B[n,:] + bias[n]) * scale
// ---------------------------------------------------------------------------
__global__ __launch_bounds__(256) void hmma_gemm16_kernel(
    const __half* __restrict__ A, const __half* __restrict__ B,
    const float* __restrict__ bias, float* __restrict__ C, float scale)
{
    __shared__ __align__(16) char smem[4 * TILEB];   // A0 A1 B0 B1 = 40KB
    const uint32_t sbase = smem_u32(smem);

    const int tid    = threadIdx.x;
    const int lane   = tid & 31;
    const int wid    = tid >> 5;
    const int warp_m = wid & 1;
    const int warp_n = wid >> 1;
    const int m0     = blockIdx.y * 128;
    const int n0     = blockIdx.x * 128;

    const int lrow = tid >> 2;
    const int lc16 = tid & 3;

    float acc[4][4][4] = {};

    auto load_chunk = [&](int c, int buf) {
        const uint32_t a_s = sbase + (uint32_t)buf * TILEB;
        const uint32_t b_s = sbase + 2u * TILEB + (uint32_t)buf * TILEB;
        #pragma unroll
        for (int t = 0; t < 2; t++) {
            const int row = lrow + t * 64;
            const uint32_t so = (uint32_t)row * ROWB + (uint32_t)lc16 * 16;
            cp_async16(a_s + so, A + (size_t)(m0 + row) * EDIM + c * 32 + lc16 * 8);
            cp_async16(b_s + so, B + (size_t)(n0 + row) * EDIM + c * 32 + lc16 * 8);
        }
        asm volatile("cp.async.commit_group;" ::: "memory");
    };

    const uint32_t lm_row = (uint32_t)(lane & 15);
    const uint32_t lm_kb  = (uint32_t)(lane >> 4) * 16;

    load_chunk(0, 0);

    for (int c = 0; c < NCH16; c++) {
        const int buf = c & 1;
        if (c + 1 < NCH16) {
            load_chunk(c + 1, buf ^ 1);
            asm volatile("cp.async.wait_group 1;" ::: "memory");
        } else {
            asm volatile("cp.async.wait_group 0;" ::: "memory");
        }
        __syncthreads();

        const uint32_t a_s = sbase + (uint32_t)buf * TILEB;
        const uint32_t b_s = sbase + 2u * TILEB + (uint32_t)buf * TILEB;

        #pragma unroll
        for (int ks = 0; ks < 2; ks++) {
            const uint32_t kb = (uint32_t)ks * 32 + lm_kb;
            uint32_t afr[4][4];
            #pragma unroll
            for (int mt = 0; mt < 4; mt++) {
                const uint32_t row = (uint32_t)(warp_m * 64 + mt * 16) + lm_row;
                ldmatrix_x4(afr[mt], a_s + row * ROWB + kb);
            }
            uint32_t bfr[2][4];
            #pragma unroll
            for (int np = 0; np < 2; np++) {
                const uint32_t row = (uint32_t)(warp_n * 32 + np * 16) + lm_row;
                ldmatrix_x4(bfr[np], b_s + row * ROWB + kb);
            }
            #pragma unroll
            for (int mt = 0; mt < 4; mt++)
                #pragma unroll
                for (int nt = 0; nt < 4; nt++)
                    mma_fp16(acc[mt][nt], afr[mt],
                             bfr[nt >> 1][nt & 1], bfr[nt >> 1][(nt & 1) + 2]);
        }
        __syncthreads();
    }

    const int q  = lane & 3;
    const int rg = lane >> 2;
    #pragma unroll
    for (int mt = 0; mt < 4; mt++) {
        #pragma unroll
        for (int half = 0; half < 2; half++) {
            const int row = m0 + warp_m * 64 + mt * 16 + rg + half * 8;
            #pragma unroll
            for (int nt = 0; nt < 4; nt++) {
                const int col = n0 + warp_n * 32 + nt * 8 + q * 2;
                float2 v;
                v.x = (acc[mt][nt][half * 2 + 0] + bias[col])     * scale;
                v.y = (acc[mt][nt][half * 2 + 1] + bias[col + 1]) * scale;
                *(float2*)(C + (size_t)row * EDIM + col) = v;
            }
        }
    }
}

// ---------------------------------------------------------------------------
// K3: fp16 single-product GEMM + fused fuzzy epilogue.
//   acc[token, n] = fp16(value)[token,:] . fp16(Wv)[n,:]   (fp32 accum)
//   F(b,h,s,d)    = 0.125 * sum_r attn[token,h,r] * (acc + bv[n])
// Tile 256x128, 512 threads (warps 4x4, 64x32 each), chunks of K=64,
// 2-stage cp.async, ONE __syncthreads per chunk. Writes g_Fh fp16 in
// (b,h,s,d) row order (matches reference transpose+reshape).
// ---------------------------------------------------------------------------
__global__ void __launch_bounds__(512, 1) hmma_fused_v4_kernel(const float* __restrict__ bv)
{
    extern __shared__ __align__(16) char smem[];
    const uint32_t sbase = smem_u32(smem);

    const int tid    = threadIdx.x;
    const int lane   = tid & 31;
    const int wid    = tid >> 5;
    const int warp_m = wid & 3;     // 4 x 64 rows
    const int warp_n = wid >> 2;    // 4 x 32 cols
    const int m0     = blockIdx.y * K3_TM;   // token base
    const int n0     = blockIdx.x * K3_TN;   // Wv-row base

    float acc[4][4][4] = {};

    // row layout: 128B chunk data + 16B pad (RX=144, conflict-free ldmatrix)
    auto load_chunk = [&](int c, int buf) {
        const uint32_t s0 = sbase + (uint32_t)buf * K3_STAGE;
        #pragma unroll
        for (int i = 0; i < 4; i++) {        // A: 256 rows x 8 x 16B
            const int idx = tid + i * 512;
            const int row = idx >> 3;
            const int c16 = idx & 7;
            cp_async16(s0 + (uint32_t)row * RX + (uint32_t)c16 * 16,
                       g_Vh + (size_t)(m0 + row) * EDIM + c * 64 + c16 * 8);
        }
        #pragma unroll
        for (int i = 0; i < 2; i++) {        // B: 128 rows x 8 x 16B
            const int idx = tid + i * 512;
            const int row = idx >> 3;
            const int c16 = idx & 7;
            cp_async16(s0 + K3_AT + (uint32_t)row * RX + (uint32_t)c16 * 16,
                       g_Wvh + (size_t)(n0 + row) * EDIM + c * 64 + c16 * 8);
        }
        asm volatile("cp.async.commit_group;" ::: "memory");
    };

    const uint32_t lm_row = (uint32_t)(lane & 15);
    const uint32_t lm_kb  = (uint32_t)(lane >> 4) * 16;

    load_chunk(0, 0);

    for (int c = 0; c < K3_NCH; c++) {
        asm volatile("cp.async.wait_group 0;" ::: "memory");
        __syncthreads();
        // slot (c+1)&1 was last read in chunk c-1; safe after the sync above.
        if (c + 1 < K3_NCH) load_chunk(c + 1, (c + 1) & 1);

        const uint32_t a_s = sbase + (uint32_t)(c & 1) * K3_STAGE;
        const uint32_t b_s = a_s + K3_AT;

        #pragma unroll
        for (int ks = 0; ks < 4; ks++) {     // four K=16 steps per 64-chunk
            const uint32_t kb = (uint32_t)ks * 32 + lm_kb;
            uint32_t afr[4][4];
            uint32_t bfr[2][4];
            #pragma unroll
            for (int np = 0; np < 2; np++) {
                const uint32_t row = (uint32_t)(warp_n * 32 + np * 16) + lm_row;
                ldmatrix_x4(bfr[np], b_s + row * RX + kb);
            }
            #pragma unroll
            for (int mt = 0; mt < 4; mt++) {
                const uint32_t row = (uint32_t)(warp_m * 64 + mt * 16) + lm_row;
                ldmatrix_x4(afr[mt], a_s + row * RX + kb);
            }
            #pragma unroll
            for (int mt = 0; mt < 4; mt++)
                #pragma unroll
                for (int nt = 0; nt < 4; nt++)
                    mma_fp16(acc[mt][nt], afr[mt],
                             bfr[nt >> 1][nt & 1], bfr[nt >> 1][(nt & 1) + 2]);
        }
    }

    // -------- fused fuzzy epilogue (writes fp16 F) --------
    const int q   = lane & 3;
    const int rg  = lane >> 2;
    const int hd0 = n0 >> 4;      // first feature of tile (multiple of 8)
    const int h   = hd0 >> 6;
    const int d0c = hd0 & 63;

    float bvv[2][4];
    #pragma unroll
    for (int g = 0; g < 2; g++)
        #pragma unroll
        for (int ntl = 0; ntl < 2; ntl++)
            #pragma unroll
            for (int j = 0; j < 2; j++)
                bvv[g][ntl * 2 + j] =
                    __ldg(bv + n0 + warp_n * 32 + g * 16 + ntl * 8 + q * 2 + j);

    #pragma unroll
    for (int mt = 0; mt < 4; mt++) {
        #pragma unroll
        for (int half = 0; half < 2; half++) {
            const int rowm  = warp_m * 64 + mt * 16 + rg + half * 8;
            const int token = m0 + rowm;
            const int b     = token >> 11;
            const int s     = token & 2047;
            const float* ap = g_attn + (size_t)token * (HNUM * RNUM) + h * RNUM;
            const float at0 = ap[q * 2],     at1 = ap[q * 2 + 1];
            const float at2 = ap[q * 2 + 8], at3 = ap[q * 2 + 9];

            // (b,h,s,d) flattened to [8192 x 512]
            const int frow  = (b * HNUM + h) * 256 + (s >> 3);
            const int cbase = (s & 7) * 64;

            #pragma unroll
            for (int g = 0; g < 2; g++) {
                float p = (acc[mt][g * 2 + 0][half * 2 + 0] + bvv[g][0]) * at0
                        + (acc[mt][g * 2 + 0][half * 2 + 1] + bvv[g][1]) * at1
                        + (acc[mt][g * 2 + 1][half * 2 + 0] + bvv[g][2]) * at2
                        + (acc[mt][g * 2 + 1][half * 2 + 1] + bvv[g][3]) * at3;
                p += __shfl_down_sync(0xffffffffu, p, 2);
                p += __shfl_down_sync(0xffffffffu, p, 1);
                if (q == 0) {
                    p *= 0.125f;  // D^-0.5
                    const int col = cbase + d0c + warp_n * 2 + g;
                    g_Fh[(size_t)frow * EDIM + col] = __float2half_rn(p);
                }
            }
        }
    }
}

// ---------------------------------------------------------------------------
extern "C" void kernel_launch(void* const* d_in, const int* in_sizes, int n_in,
                              void* d_out, int out_size)
{
    const float* query = (const float*)d_in[0];
    // d_in[1] = key: unused by the reference computation
    const float* value = (const float*)d_in[2];
    const float* Wq    = (const float*)d_in[3];
    const float* bq    = (const float*)d_in[4];
    const float* Wv    = (const float*)d_in[5];
    const float* bv    = (const float*)d_in[6];
    const float* Wo    = (const float*)d_in[7];
    const float* bo    = (const float*)d_in[8];
    const float* rk    = (const float*)d_in[9];
    const float* rw    = (const float*)d_in[10];
    float* out = (float*)d_out;

    float* Qp = nullptr;
    __half *Vh = nullptr, *Wvh = nullptr, *Qh = nullptr;
    __half *Wqh = nullptr, *Woh = nullptr, *Fh = nullptr;
    cudaGetSymbolAddress((void**)&Qp,  g_Q);
    cudaGetSymbolAddress((void**)&Vh,  g_Vh);
    cudaGetSymbolAddress((void**)&Wvh, g_Wvh);
    cudaGetSymbolAddress((void**)&Qh,  g_Qh);
    cudaGetSymbolAddress((void**)&Wqh, g_Wqh);
    cudaGetSymbolAddress((void**)&Woh, g_Woh);
    cudaGetSymbolAddress((void**)&Fh,  g_Fh);

    cudaFuncSetAttribute(hmma_fused_v4_kernel,
                         cudaFuncAttributeMaxDynamicSharedMemorySize, K3_SMEM);

    dim3 blk(256);

    // fp32 -> fp16 conversions
    convh_kernel<<<dim3((TOK   * EDIM) / 1024), blk>>>(value, Vh);
    convh_kernel<<<dim3((ERDIM * EDIM) / 1024), blk>>>(Wv, Wvh);
    convh_kernel<<<dim3((TOK   * EDIM) / 1024), blk>>>(query, Qh);
    convh_kernel<<<dim3((EDIM  * EDIM) / 1024), blk>>>(Wq, Wqh);
    convh_kernel<<<dim3((EDIM  * EDIM) / 1024), blk>>>(Wo, Woh);
    prep_iw2_kernel<<<dim3((HNUM * RNUM * DDIM + 255) / 256), blk>>>(rw);

    // K1: q projection (scaled), fp16 single product
    hmma_gemm16_kernel<<<dim3(EDIM / 128, TOK / 128), blk>>>(
        Qh, Wqh, bq, Qp, 0.125f);

    // K2: fuzzy rule attention
    attn_kernel<<<dim3(TOK), blk>>>(rk);

    // K3: fused v-GEMM + rule reduction, fp16 single product
    hmma_fused_v4_kernel<<<dim3(ERDIM / K3_TN, TOK / K3_TM), dim3(512), K3_SMEM>>>(bv);

    // K4: output projection, fp16 single product (reads g_Fh directly)
    hmma_gemm16_kernel<<<dim3(EDIM / 128, TOK / 128), blk>>>(
        Fh, Woh, bo, out, 1.0f);
}

// round 12
// speedup vs baseline: 2.3032x; 1.1141x over previous
#include <cuda_runtime.h>
#include <cuda_fp16.h>
#include <cstdint>

// Problem constants (fixed by setup_inputs)
#define BATCH 4
#define SEQ   2048
#define EDIM  512
#define HNUM  8
#define RNUM  16
#define DDIM  64
#define TOK   (BATCH * SEQ)      // 8192 tokens
#define ERDIM (EDIM * RNUM)      // 8192 Wv rows

// K1/K4 (fp16, K=512, tile 128x128, BK=32)
#define NCH16 16
#define ROWB  80                 // 64B data + 16B pad
#define TILEB (128 * ROWB)       // 10240

// K3 (fp16, K=512, tile 128x128, BK=64, 2 CTAs/SM)
#define K5_NCH   8               // 512 / 64
#define K5_RX    144             // 128B data + 16B pad
#define K5_AT    (128 * K5_RX)   // 18432 (A tile == B tile)
#define K5_STAGE (2 * K5_AT)     // 36864
#define K5_SMEM  (2 * K5_STAGE)  // 73728 (2 stages)

// Scratch (allocation-free: __device__ globals)
__device__ float g_Q[TOK * EDIM];              // scaled query projection (fp32)
__device__ float g_attn[TOK * HNUM * RNUM];    // softmax over rules
__device__ float g_iw2[HNUM * RNUM * DDIM];    // 1 / rules_widths^2
__device__ __half g_Vh[(size_t)TOK   * EDIM];  // value  fp16
__device__ __half g_Qh[(size_t)TOK   * EDIM];  // query  fp16
__device__ __half g_Wvh[(size_t)ERDIM * EDIM]; // Wv     fp16
__device__ __half g_Wqh[(size_t)EDIM * EDIM];  // Wq     fp16
__device__ __half g_Woh[(size_t)EDIM * EDIM];  // Wo     fp16
__device__ __half g_Fh[(size_t)TOK   * EDIM];  // F fp16, (b,h,s,d) row order

// ---------------------------------------------------------------------------
// Portable PTX helpers (sm_80+)
// ---------------------------------------------------------------------------
__device__ __forceinline__ uint32_t smem_u32(const void* p) {
    uint32_t a;
    asm("{ .reg .u64 t; cvta.to.shared.u64 t, %1; cvt.u32.u64 %0, t; }"
        : "=r"(a) : "l"(p));
    return a;
}
__device__ __forceinline__ void cp_async16(uint32_t dst, const void* src) {
    asm volatile("cp.async.cg.shared.global [%0], [%1], 16;"
                 :: "r"(dst), "l"(src) : "memory");
}
__device__ __forceinline__ void ldmatrix_x4(uint32_t* r, uint32_t addr) {
    asm volatile("ldmatrix.sync.aligned.m8n8.x4.shared.b16 {%0,%1,%2,%3}, [%4];"
                 : "=r"(r[0]), "=r"(r[1]), "=r"(r[2]), "=r"(r[3]) : "r"(addr));
}
__device__ __forceinline__ void mma_fp16(float* c, const uint32_t* a,
                                         uint32_t b0, uint32_t b1) {
    asm volatile(
        "mma.sync.aligned.m16n8k16.row.col.f32.f16.f16.f32 "
        "{%0,%1,%2,%3}, {%4,%5,%6,%7}, {%8,%9}, {%0,%1,%2,%3};"
        : "+f"(c[0]), "+f"(c[1]), "+f"(c[2]), "+f"(c[3])
        : "r"(a[0]), "r"(a[1]), "r"(a[2]), "r"(a[3]), "r"(b0), "r"(b1));
}

// ---------------------------------------------------------------------------
// Merged fp32 -> fp16 converts (float4 granularity).
// convA: value then query (TOK*EDIM each).
// convB: Wv (ERDIM*EDIM), Wq (EDIM*EDIM), Wo (EDIM*EDIM).
// ---------------------------------------------------------------------------
#define N4_TOK  (TOK * EDIM / 4)     // 1048576
#define N4_WV   (ERDIM * EDIM / 4)   // 1048576
#define N4_W    (EDIM * EDIM / 4)    // 65536

__device__ __forceinline__ void conv4(const float* __restrict__ s,
                                      __half* __restrict__ d, size_t i) {
    float4 v = ((const float4*)s)[i];
    *(__half2*)(d + i * 4)     = __halves2half2(__float2half_rn(v.x), __float2half_rn(v.y));
    *(__half2*)(d + i * 4 + 2) = __halves2half2(__float2half_rn(v.z), __float2half_rn(v.w));
}

__global__ __launch_bounds__(256) void convA_kernel(
    const float* __restrict__ value, const float* __restrict__ query)
{
    size_t i = (size_t)blockIdx.x * 256 + threadIdx.x;
    if (i < N4_TOK) conv4(value, g_Vh, i);
    else            conv4(query, g_Qh, i - N4_TOK);
}

__global__ __launch_bounds__(256) void convB_kernel(
    const float* __restrict__ Wv, const float* __restrict__ Wq,
    const float* __restrict__ Wo)
{
    size_t i = (size_t)blockIdx.x * 256 + threadIdx.x;
    if (i < N4_WV)            conv4(Wv, g_Wvh, i);
    else if (i < N4_WV + N4_W) conv4(Wq, g_Wqh, i - N4_WV);
    else                       conv4(Wo, g_Woh, i - N4_WV - N4_W);
}

__global__ __launch_bounds__(256) void prep_iw2_kernel(const float* __restrict__ rw)
{
    int i = blockIdx.x * 256 + threadIdx.x;
    if (i < HNUM * RNUM * DDIM) {
        float t = 1.0f / rw[i];
        g_iw2[i] = t * t;
    }
}

// ---------------------------------------------------------------------------
// K2: fuzzy rule attention. One warp per (token, head); all 32 lanes active.
// ---------------------------------------------------------------------------
__global__ __launch_bounds__(256) void attn_kernel(const float* __restrict__ rk)
{
    __shared__ float qs[EDIM];
    const int token = blockIdx.x;
    {
        const float4* src = (const float4*)(g_Q + (size_t)token * EDIM);
        float4* dst = (float4*)qs;
        if (threadIdx.x < 128) dst[threadIdx.x] = src[threadIdx.x];
    }
    __syncthreads();

    const int h    = threadIdx.x >> 5;
    const int lane = threadIdx.x & 31;

    const float qa = qs[h * DDIM + lane];
    const float qb = qs[h * DDIM + lane + 32];

    float z = 0.f;
    #pragma unroll
    for (int r = 0; r < RNUM; r++) {
        const float* rp = rk    + (size_t)(h * RNUM + r) * DDIM;
        const float* wp = g_iw2 + (size_t)(h * RNUM + r) * DDIM;
        float d0 = qa - rp[lane];
        float d1 = qb - rp[lane + 32];
        float s  = d0 * d0 * wp[lane] + d1 * d1 * wp[lane + 32];
        #pragma unroll
        for (int o = 16; o; o >>= 1) s += __shfl_xor_sync(0xffffffffu, s, o);
        if (lane == r) z = s;
    }

    if (lane < 16) {
        z *= -0.5f / DDIM;
        float m = z;
        #pragma unroll
        for (int o = 8; o; o >>= 1) m = fmaxf(m, __shfl_xor_sync(0x0000ffffu, m, o));
        float e = expf(z - m);
        float sum = e;
        #pragma unroll
        for (int o = 8; o; o >>= 1) sum += __shfl_xor_sync(0x0000ffffu, sum, o);
        g_attn[(size_t)token * (HNUM * RNUM) + h * RNUM + lane] = e / sum;
    }
}

// ---------------------------------------------------------------------------
// K1/K4: plain fp16 HMMA GEMM, K=512, tile 128x128, double-buffered.
// ---------------------------------------------------------------------------
__global__ __launch_bounds__(256) void hmma_gemm16_kernel(
    const __half* __restrict__ A, const __half* __restrict__ B,
    const float* __restrict__ bias, float* __restrict__ C, float scale)
{
    __shared__ __align__(16) char smem[4 * TILEB];
    const uint32_t sbase = smem_u32(smem);

    const int tid    = threadIdx.x;
    const int lane   = tid & 31;
    const int wid    = tid >> 5;
    const int warp_m = wid & 1;
    const int warp_n = wid >> 1;
    const int m0     = blockIdx.y * 128;
    const int n0     = blockIdx.x * 128;

    const int lrow = tid >> 2;
    const int lc16 = tid & 3;

    float acc[4][4][4] = {};

    auto load_chunk = [&](int c, int buf) {
        const uint32_t a_s = sbase + (uint32_t)buf * TILEB;
        const uint32_t b_s = sbase + 2u * TILEB + (uint32_t)buf * TILEB;
        #pragma unroll
        for (int t = 0; t < 2; t++) {
            const int row = lrow + t * 64;
            const uint32_t so = (uint32_t)row * ROWB + (uint32_t)lc16 * 16;
            cp_async16(a_s + so, A + (size_t)(m0 + row) * EDIM + c * 32 + lc16 * 8);
            cp_async16(b_s + so, B + (size_t)(n0 + row) * EDIM + c * 32 + lc16 * 8);
        }
        asm volatile("cp.async.commit_group;" ::: "memory");
    };

    const uint32_t lm_row = (uint32_t)(lane & 15);
    const uint32_t lm_kb  = (uint32_t)(lane >> 4) * 16;

    load_chunk(0, 0);

    for (int c = 0; c < NCH16; c++) {
        const int buf = c & 1;
        if (c + 1 < NCH16) {
            load_chunk(c + 1, buf ^ 1);
            asm volatile("cp.async.wait_group 1;" ::: "memory");
        } else {
            asm volatile("cp.async.wait_group 0;" ::: "memory");
        }
        __syncthreads();

        const uint32_t a_s = sbase + (uint32_t)buf * TILEB;
        const uint32_t b_s = sbase + 2u * TILEB + (uint32_t)buf * TILEB;

        #pragma unroll
        for (int ks = 0; ks < 2; ks++) {
            const uint32_t kb = (uint32_t)ks * 32 + lm_kb;
            uint32_t afr[4][4];
            #pragma unroll
            for (int mt = 0; mt < 4; mt++) {
                const uint32_t row = (uint32_t)(warp_m * 64 + mt * 16) + lm_row;
                ldmatrix_x4(afr[mt], a_s + row * ROWB + kb);
            }
            uint32_t bfr[2][4];
            #pragma unroll
            for (int np = 0; np < 2; np++) {
                const uint32_t row = (uint32_t)(warp_n * 32 + np * 16) + lm_row;
                ldmatrix_x4(bfr[np], b_s + row * ROWB + kb);
            }
            #pragma unroll
            for (int mt = 0; mt < 4; mt++)
                #pragma unroll
                for (int nt = 0; nt < 4; nt++)
                    mma_fp16(acc[mt][nt], afr[mt],
                             bfr[nt >> 1][nt & 1], bfr[nt >> 1][(nt & 1) + 2]);
        }
        __syncthreads();
    }

    const int q  = lane & 3;
    const int rg = lane >> 2;
    #pragma unroll
    for (int mt = 0; mt < 4; mt++) {
        #pragma unroll
        for (int half = 0; half < 2; half++) {
            const int row = m0 + warp_m * 64 + mt * 16 + rg + half * 8;
            #pragma unroll
            for (int nt = 0; nt < 4; nt++) {
                const int col = n0 + warp_n * 32 + nt * 8 + q * 2;
                float2 v;
                v.x = (acc[mt][nt][half * 2 + 0] + bias[col])     * scale;
                v.y = (acc[mt][nt][half * 2 + 1] + bias[col + 1]) * scale;
                *(float2*)(C + (size_t)row * EDIM + col) = v;
            }
        }
    }
}

// ---------------------------------------------------------------------------
// K3: fp16 single-product GEMM + fused fuzzy epilogue.
// Tile 128x128, 256 threads (warps 2(M) x 4(N)), BK=64 chunks, 2-stage
// cp.async, 2 CTAs/SM (72KB smem each) so the second CTA hides sync/tail
// bubbles. Writes g_Fh fp16 in (b,h,s,d) row order.
// ---------------------------------------------------------------------------
__global__ void __launch_bounds__(256, 2) hmma_fused_v5_kernel(const float* __restrict__ bv)
{
    extern __shared__ __align__(16) char smem[];
    const uint32_t sbase = smem_u32(smem);

    const int tid    = threadIdx.x;
    const int lane   = tid & 31;
    const int wid    = tid >> 5;
    const int warp_m = wid & 1;     // 2 x 64 rows
    const int warp_n = wid >> 1;    // 4 x 32 cols
    const int m0     = blockIdx.y * 128;   // token base
    const int n0     = blockIdx.x * 128;   // Wv-row base

    float acc[4][4][4] = {};

    // row layout: 128B chunk data + 16B pad (K5_RX=144)
    auto load_chunk = [&](int c, int buf) {
        const uint32_t s0 = sbase + (uint32_t)buf * K5_STAGE;
        #pragma unroll
        for (int i = 0; i < 4; i++) {        // A: 128 rows x 8 x 16B
            const int idx = tid + i * 256;
            const int row = idx >> 3;
            const int c16 = idx & 7;
            cp_async16(s0 + (uint32_t)row * K5_RX + (uint32_t)c16 * 16,
                       g_Vh + (size_t)(m0 + row) * EDIM + c * 64 + c16 * 8);
        }
        #pragma unroll
        for (int i = 0; i < 4; i++) {        // B: 128 rows x 8 x 16B
            const int idx = tid + i * 256;
            const int row = idx >> 3;
            const int c16 = idx & 7;
            cp_async16(s0 + K5_AT + (uint32_t)row * K5_RX + (uint32_t)c16 * 16,
                       g_Wvh + (size_t)(n0 + row) * EDIM + c * 64 + c16 * 8);
        }
        asm volatile("cp.async.commit_group;" ::: "memory");
    };

    const uint32_t lm_row = (uint32_t)(lane & 15);
    const uint32_t lm_kb  = (uint32_t)(lane >> 4) * 16;

    load_chunk(0, 0);

    for (int c = 0; c < K5_NCH; c++) {
        asm volatile("cp.async.wait_group 0;" ::: "memory");
        __syncthreads();
        // slot (c+1)&1 was last read in chunk c-1; safe after the sync above.
        if (c + 1 < K5_NCH) load_chunk(c + 1, (c + 1) & 1);

        const uint32_t a_s = sbase + (uint32_t)(c & 1) * K5_STAGE;
        const uint32_t b_s = a_s + K5_AT;

        #pragma unroll
        for (int ks = 0; ks < 4; ks++) {     // four K=16 steps per 64-chunk
            const uint32_t kb = (uint32_t)ks * 32 + lm_kb;
            uint32_t afr[4][4];
            uint32_t bfr[2][4];
            #pragma unroll
            for (int np = 0; np < 2; np++) {
                const uint32_t row = (uint32_t)(warp_n * 32 + np * 16) + lm_row;
                ldmatrix_x4(bfr[np], b_s + row * K5_RX + kb);
            }
            #pragma unroll
            for (int mt = 0; mt < 4; mt++) {
                const uint32_t row = (uint32_t)(warp_m * 64 + mt * 16) + lm_row;
                ldmatrix_x4(afr[mt], a_s + row * K5_RX + kb);
            }
            #pragma unroll
            for (int mt = 0; mt < 4; mt++)
                #pragma unroll
                for (int nt = 0; nt < 4; nt++)
                    mma_fp16(acc[mt][nt], afr[mt],
                             bfr[nt >> 1][nt & 1], bfr[nt >> 1][(nt & 1) + 2]);
        }
    }

    // -------- fused fuzzy epilogue (writes fp16 F) --------
    const int q   = lane & 3;
    const int rg  = lane >> 2;
    const int hd0 = n0 >> 4;      // first feature of tile (multiple of 8)
    const int h   = hd0 >> 6;
    const int d0c = hd0 & 63;

    float bvv[2][4];
    #pragma unroll
    for (int g = 0; g < 2; g++)
        #pragma unroll
        for (int ntl = 0; ntl < 2; ntl++)
            #pragma unroll
            for (int j = 0; j < 2; j++)
                bvv[g][ntl * 2 + j] =
                    __ldg(bv + n0 + warp_n * 32 + g * 16 + ntl * 8 + q * 2 + j);

    #pragma unroll
    for (int mt = 0; mt < 4; mt++) {
        #pragma unroll
        for (int half = 0; half < 2; half++) {
            const int rowm  = warp_m * 64 + mt * 16 + rg + half * 8;
            const int token = m0 + rowm;
            const int b     = token >> 11;
            const int s     = token & 2047;
            const float* ap = g_attn + (size_t)token * (HNUM * RNUM) + h * RNUM;
            const float at0 = ap[q * 2],     at1 = ap[q * 2 + 1];
            const float at2 = ap[q * 2 + 8], at3 = ap[q * 2 + 9];

            // (b,h,s,d) flattened to [8192 x 512]
            const int frow  = (b * HNUM + h) * 256 + (s >> 3);
            const int cbase = (s & 7) * 64;

            #pragma unroll
            for (int g = 0; g < 2; g++) {
                float p = (acc[mt][g * 2 + 0][half * 2 + 0] + bvv[g][0]) * at0
                        + (acc[mt][g * 2 + 0][half * 2 + 1] + bvv[g][1]) * at1
                        + (acc[mt][g * 2 + 1][half * 2 + 0] + bvv[g][2]) * at2
                        + (acc[mt][g * 2 + 1][half * 2 + 1] + bvv[g][3]) * at3;
                p += __shfl_down_sync(0xffffffffu, p, 2);
                p += __shfl_down_sync(0xffffffffu, p, 1);
                if (q == 0) {
                    p *= 0.125f;  // D^-0.5
                    const int col = cbase + d0c + warp_n * 2 + g;
                    g_Fh[(size_t)frow * EDIM + col] = __float2half_rn(p);
                }
            }
        }
    }
}

// ---------------------------------------------------------------------------
extern "C" void kernel_launch(void* const* d_in, const int* in_sizes, int n_in,
                              void* d_out, int out_size)
{
    const float* query = (const float*)d_in[0];
    // d_in[1] = key: unused by the reference computation
    const float* value = (const float*)d_in[2];
    const float* Wq    = (const float*)d_in[3];
    const float* bq    = (const float*)d_in[4];
    const float* Wv    = (const float*)d_in[5];
    const float* bv    = (const float*)d_in[6];
    const float* Wo    = (const float*)d_in[7];
    const float* bo    = (const float*)d_in[8];
    const float* rk    = (const float*)d_in[9];
    const float* rw    = (const float*)d_in[10];
    float* out = (float*)d_out;

    float* Qp = nullptr;
    __half *Qh = nullptr, *Wqh = nullptr, *Woh = nullptr, *Fh = nullptr;
    cudaGetSymbolAddress((void**)&Qp,  g_Q);
    cudaGetSymbolAddress((void**)&Qh,  g_Qh);
    cudaGetSymbolAddress((void**)&Wqh, g_Wqh);
    cudaGetSymbolAddress((void**)&Woh, g_Woh);
    cudaGetSymbolAddress((void**)&Fh,  g_Fh);

    cudaFuncSetAttribute(hmma_fused_v5_kernel,
                         cudaFuncAttributeMaxDynamicSharedMemorySize, K5_SMEM);

    dim3 blk(256);

    // 1-2: merged fp32 -> fp16 conversions
    convA_kernel<<<dim3((2 * N4_TOK) / 256), blk>>>(value, query);
    convB_kernel<<<dim3((N4_WV + 2 * N4_W) / 256), blk>>>(Wv, Wq, Wo);
    // 3: rule width preprocessing
    prep_iw2_kernel<<<dim3((HNUM * RNUM * DDIM + 255) / 256), blk>>>(rw);

    // 4: K1 q projection (scaled)
    hmma_gemm16_kernel<<<dim3(EDIM / 128, TOK / 128), blk>>>(
        Qh, Wqh, bq, Qp, 0.125f);

    // 5: K2 fuzzy rule attention
    attn_kernel<<<dim3(TOK), blk>>>(rk);

    // 6: K3 fused v-GEMM + rule reduction (ncu -s 5 -c 1 captures this one)
    hmma_fused_v5_kernel<<<dim3(ERDIM / 128, TOK / 128), blk, K5_SMEM>>>(bv);

    // 7: K4 output projection (reads g_Fh directly)
    hmma_gemm16_kernel<<<dim3(EDIM / 128, TOK / 128), blk>>>(
        Fh, Woh, bo, out, 1.0f);
}

// round 13
// speedup vs baseline: 2.3038x; 1.0003x over previous
#include <cuda_runtime.h>
#include <cuda_fp16.h>
#include <cstdint>

// Problem constants (fixed by setup_inputs)
#define BATCH 4
#define SEQ   2048
#define EDIM  512
#define HNUM  8
#define RNUM  16
#define DDIM  64
#define TOK   (BATCH * SEQ)      // 8192 tokens
#define ERDIM (EDIM * RNUM)      // 8192 Wv rows

// K1/K4 (fp16, K=512, tile 128x128, BK=32) -- unchanged, proven
#define NCH16 16
#define ROWB  80                 // 64B data + 16B pad
#define TILEB (128 * ROWB)       // 10240

// K3 (fp16, K=512, tile 128x128, BK=64, 128 threads, warp tile 64x64)
#define K6_NCH   8               // 512 / 64
#define K6_RX    144             // 128B data + 16B pad
#define K6_AT    (128 * K6_RX)   // 18432 (A tile == B tile)
#define K6_STAGE (2 * K6_AT)     // 36864
#define K6_SMEM  (2 * K6_STAGE)  // 73728 (2 stages)

// Scratch (allocation-free: __device__ globals)
__device__ float g_Q[TOK * EDIM];              // scaled query projection (fp32)
__device__ float g_attn[TOK * HNUM * RNUM];    // softmax over rules
__device__ float g_iw2[HNUM * RNUM * DDIM];    // 1 / rules_widths^2
__device__ __half g_Vh[(size_t)TOK   * EDIM];  // value  fp16
__device__ __half g_Qh[(size_t)TOK   * EDIM];  // query  fp16
__device__ __half g_Wvh[(size_t)ERDIM * EDIM]; // Wv     fp16
__device__ __half g_Wqh[(size_t)EDIM * EDIM];  // Wq     fp16
__device__ __half g_Woh[(size_t)EDIM * EDIM];  // Wo     fp16
__device__ __half g_Fh[(size_t)TOK   * EDIM];  // F fp16, (b,h,s,d) row order

// ---------------------------------------------------------------------------
// Portable PTX helpers (sm_80+)
// ---------------------------------------------------------------------------
__device__ __forceinline__ uint32_t smem_u32(const void* p) {
    uint32_t a;
    asm("{ .reg .u64 t; cvta.to.shared.u64 t, %1; cvt.u32.u64 %0, t; }"
        : "=r"(a) : "l"(p));
    return a;
}
__device__ __forceinline__ void cp_async16(uint32_t dst, const void* src) {
    asm volatile("cp.async.cg.shared.global [%0], [%1], 16;"
                 :: "r"(dst), "l"(src) : "memory");
}
__device__ __forceinline__ void ldmatrix_x4(uint32_t* r, uint32_t addr) {
    asm volatile("ldmatrix.sync.aligned.m8n8.x4.shared.b16 {%0,%1,%2,%3}, [%4];"
                 : "=r"(r[0]), "=r"(r[1]), "=r"(r[2]), "=r"(r[3]) : "r"(addr));
}
__device__ __forceinline__ void mma_fp16(float* c, const uint32_t* a,
                                         uint32_t b0, uint32_t b1) {
    asm volatile(
        "mma.sync.aligned.m16n8k16.row.col.f32.f16.f16.f32 "
        "{%0,%1,%2,%3}, {%4,%5,%6,%7}, {%8,%9}, {%0,%1,%2,%3};"
        : "+f"(c[0]), "+f"(c[1]), "+f"(c[2]), "+f"(c[3])
        : "r"(a[0]), "r"(a[1]), "r"(a[2]), "r"(a[3]), "r"(b0), "r"(b1));
}

// ---------------------------------------------------------------------------
// Merged fp32 -> fp16 converts (float4 granularity).
// ---------------------------------------------------------------------------
#define N4_TOK  (TOK * EDIM / 4)     // 1048576
#define N4_WV   (ERDIM * EDIM / 4)   // 1048576
#define N4_W    (EDIM * EDIM / 4)    // 65536

__device__ __forceinline__ void conv4(const float* __restrict__ s,
                                      __half* __restrict__ d, size_t i) {
    float4 v = ((const float4*)s)[i];
    *(__half2*)(d + i * 4)     = __halves2half2(__float2half_rn(v.x), __float2half_rn(v.y));
    *(__half2*)(d + i * 4 + 2) = __halves2half2(__float2half_rn(v.z), __float2half_rn(v.w));
}

__global__ __launch_bounds__(256) void convA_kernel(
    const float* __restrict__ value, const float* __restrict__ query)
{
    size_t i = (size_t)blockIdx.x * 256 + threadIdx.x;
    if (i < N4_TOK) conv4(value, g_Vh, i);
    else            conv4(query, g_Qh, i - N4_TOK);
}

__global__ __launch_bounds__(256) void convB_kernel(
    const float* __restrict__ Wv, const float* __restrict__ Wq,
    const float* __restrict__ Wo)
{
    size_t i = (size_t)blockIdx.x * 256 + threadIdx.x;
    if (i < N4_WV)             conv4(Wv, g_Wvh, i);
    else if (i < N4_WV + N4_W) conv4(Wq, g_Wqh, i - N4_WV);
    else                       conv4(Wo, g_Woh, i - N4_WV - N4_W);
}

__global__ __launch_bounds__(256) void prep_iw2_kernel(const float* __restrict__ rw)
{
    int i = blockIdx.x * 256 + threadIdx.x;
    if (i < HNUM * RNUM * DDIM) {
        float t = 1.0f / rw[i];
        g_iw2[i] = t * t;
    }
}

// ---------------------------------------------------------------------------
// K2: fuzzy rule attention. One warp per (token, head); all 32 lanes active.
// ---------------------------------------------------------------------------
__global__ __launch_bounds__(256) void attn_kernel(const float* __restrict__ rk)
{
    __shared__ float qs[EDIM];
    const int token = blockIdx.x;
    {
        const float4* src = (const float4*)(g_Q + (size_t)token * EDIM);
        float4* dst = (float4*)qs;
        if (threadIdx.x < 128) dst[threadIdx.x] = src[threadIdx.x];
    }
    __syncthreads();

    const int h    = threadIdx.x >> 5;
    const int lane = threadIdx.x & 31;

    const float qa = qs[h * DDIM + lane];
    const float qb = qs[h * DDIM + lane + 32];

    float z = 0.f;
    #pragma unroll
    for (int r = 0; r < RNUM; r++) {
        const float* rp = rk    + (size_t)(h * RNUM + r) * DDIM;
        const float* wp = g_iw2 + (size_t)(h * RNUM + r) * DDIM;
        float d0 = qa - rp[lane];
        float d1 = qb - rp[lane + 32];
        float s  = d0 * d0 * wp[lane] + d1 * d1 * wp[lane + 32];
        #pragma unroll
        for (int o = 16; o; o >>= 1) s += __shfl_xor_sync(0xffffffffu, s, o);
        if (lane == r) z = s;
    }

    if (lane < 16) {
        z *= -0.5f / DDIM;
        float m = z;
        #pragma unroll
        for (int o = 8; o; o >>= 1) m = fmaxf(m, __shfl_xor_sync(0x0000ffffu, m, o));
        float e = expf(z - m);
        float sum = e;
        #pragma unroll
        for (int o = 8; o; o >>= 1) sum += __shfl_xor_sync(0x0000ffffu, sum, o);
        g_attn[(size_t)token * (HNUM * RNUM) + h * RNUM + lane] = e / sum;
    }
}

// ---------------------------------------------------------------------------
// K1/K4: plain fp16 HMMA GEMM, K=512, tile 128x128, double-buffered (proven).
// ---------------------------------------------------------------------------
__global__ __launch_bounds__(256) void hmma_gemm16_kernel(
    const __half* __restrict__ A, const __half* __restrict__ B,
    const float* __restrict__ bias, float* __restrict__ C, float scale)
{
    __shared__ __align__(16) char smem[4 * TILEB];
    const uint32_t sbase = smem_u32(smem);

    const int tid    = threadIdx.x;
    const int lane   = tid & 31;
    const int wid    = tid >> 5;
    const int warp_m = wid & 1;
    const int warp_n = wid >> 1;
    const int m0     = blockIdx.y * 128;
    const int n0     = blockIdx.x * 128;

    const int lrow = tid >> 2;
    const int lc16 = tid & 3;

    float acc[4][4][4] = {};

    auto load_chunk = [&](int c, int buf) {
        const uint32_t a_s = sbase + (uint32_t)buf * TILEB;
        const uint32_t b_s = sbase + 2u * TILEB + (uint32_t)buf * TILEB;
        #pragma unroll
        for (int t = 0; t < 2; t++) {
            const int row = lrow + t * 64;
            const uint32_t so = (uint32_t)row * ROWB + (uint32_t)lc16 * 16;
            cp_async16(a_s + so, A + (size_t)(m0 + row) * EDIM + c * 32 + lc16 * 8);
            cp_async16(b_s + so, B + (size_t)(n0 + row) * EDIM + c * 32 + lc16 * 8);
        }
        asm volatile("cp.async.commit_group;" ::: "memory");
    };

    const uint32_t lm_row = (uint32_t)(lane & 15);
    const uint32_t lm_kb  = (uint32_t)(lane >> 4) * 16;

    load_chunk(0, 0);

    for (int c = 0; c < NCH16; c++) {
        const int buf = c & 1;
        if (c + 1 < NCH16) {
            load_chunk(c + 1, buf ^ 1);
            asm volatile("cp.async.wait_group 1;" ::: "memory");
        } else {
            asm volatile("cp.async.wait_group 0;" ::: "memory");
        }
        __syncthreads();

        const uint32_t a_s = sbase + (uint32_t)buf * TILEB;
        const uint32_t b_s = sbase + 2u * TILEB + (uint32_t)buf * TILEB;

        #pragma unroll
        for (int ks = 0; ks < 2; ks++) {
            const uint32_t kb = (uint32_t)ks * 32 + lm_kb;
            uint32_t afr[4][4];
            #pragma unroll
            for (int mt = 0; mt < 4; mt++) {
                const uint32_t row = (uint32_t)(warp_m * 64 + mt * 16) + lm_row;
                ldmatrix_x4(afr[mt], a_s + row * ROWB + kb);
            }
            uint32_t bfr[2][4];
            #pragma unroll
            for (int np = 0; np < 2; np++) {
                const uint32_t row = (uint32_t)(warp_n * 32 + np * 16) + lm_row;
                ldmatrix_x4(bfr[np], b_s + row * ROWB + kb);
            }
            #pragma unroll
            for (int mt = 0; mt < 4; mt++)
                #pragma unroll
                for (int nt = 0; nt < 4; nt++)
                    mma_fp16(acc[mt][nt], afr[mt],
                             bfr[nt >> 1][nt & 1], bfr[nt >> 1][(nt & 1) + 2]);
        }
        __syncthreads();
    }

    const int q  = lane & 3;
    const int rg = lane >> 2;
    #pragma unroll
    for (int mt = 0; mt < 4; mt++) {
        #pragma unroll
        for (int half = 0; half < 2; half++) {
            const int row = m0 + warp_m * 64 + mt * 16 + rg + half * 8;
            #pragma unroll
            for (int nt = 0; nt < 4; nt++) {
                const int col = n0 + warp_n * 32 + nt * 8 + q * 2;
                float2 v;
                v.x = (acc[mt][nt][half * 2 + 0] + bias[col])     * scale;
                v.y = (acc[mt][nt][half * 2 + 1] + bias[col + 1]) * scale;
                *(float2*)(C + (size_t)row * EDIM + col) = v;
            }
        }
    }
}

// ---------------------------------------------------------------------------
// K3 v6: fp16 single-product GEMM + fused fuzzy epilogue.
// Tile 128x128, 128 threads = 4 warps in 2(M) x 2(N); warp tile 64x64:
// 32 independent MMAs per 8 ldmatrix per k16 step (2x ILP, half the LDSM
// of v5). __launch_bounds__(128,2): 256-reg cap gives ptxas room to hoist
// fragment loads across ks steps; 2 CTAs/SM hide sync/tail.
// Writes g_Fh fp16 in (b,h,s,d) row order.
// ---------------------------------------------------------------------------
__global__ void __launch_bounds__(128, 2) hmma_fused_v6_kernel(const float* __restrict__ bv)
{
    extern __shared__ __align__(16) char smem[];
    const uint32_t sbase = smem_u32(smem);

    const int tid    = threadIdx.x;
    const int lane   = tid & 31;
    const int wid    = tid >> 5;
    const int warp_m = wid & 1;     // 2 x 64 rows
    const int warp_n = wid >> 1;    // 2 x 64 cols
    const int m0     = blockIdx.y * 128;   // token base
    const int n0     = blockIdx.x * 128;   // Wv-row base

    float acc[4][8][4] = {};   // [mt 16-row][nt 8-col][frag]

    // row layout: 128B chunk data + 16B pad (K6_RX=144)
    auto load_chunk = [&](int c, int buf) {
        const uint32_t s0 = sbase + (uint32_t)buf * K6_STAGE;
        #pragma unroll
        for (int i = 0; i < 8; i++) {        // A: 128 rows x 8 x 16B
            const int idx = tid + i * 128;
            const int row = idx >> 3;
            const int c16 = idx & 7;
            cp_async16(s0 + (uint32_t)row * K6_RX + (uint32_t)c16 * 16,
                       g_Vh + (size_t)(m0 + row) * EDIM + c * 64 + c16 * 8);
        }
        #pragma unroll
        for (int i = 0; i < 8; i++) {        // B: 128 rows x 8 x 16B
            const int idx = tid + i * 128;
            const int row = idx >> 3;
            const int c16 = idx & 7;
            cp_async16(s0 + K6_AT + (uint32_t)row * K6_RX + (uint32_t)c16 * 16,
                       g_Wvh + (size_t)(n0 + row) * EDIM + c * 64 + c16 * 8);
        }
        asm volatile("cp.async.commit_group;" ::: "memory");
    };

    const uint32_t lm_row = (uint32_t)(lane & 15);
    const uint32_t lm_kb  = (uint32_t)(lane >> 4) * 16;

    load_chunk(0, 0);

    for (int c = 0; c < K6_NCH; c++) {
        asm volatile("cp.async.wait_group 0;" ::: "memory");
        __syncthreads();
        // slot (c+1)&1 was last read in chunk c-1; safe after the sync above.
        if (c + 1 < K6_NCH) load_chunk(c + 1, (c + 1) & 1);

        const uint32_t a_s = sbase + (uint32_t)(c & 1) * K6_STAGE;
        const uint32_t b_s = a_s + K6_AT;

        #pragma unroll
        for (int ks = 0; ks < 4; ks++) {     // four K=16 steps per 64-chunk
            const uint32_t kb = (uint32_t)ks * 32 + lm_kb;
            uint32_t afr[4][4];
            uint32_t bfr[4][4];
            #pragma unroll
            for (int nb = 0; nb < 4; nb++) {  // B: 64 cols = 4 x 16-row blocks
                const uint32_t row = (uint32_t)(warp_n * 64 + nb * 16) + lm_row;
                ldmatrix_x4(bfr[nb], b_s + row * K6_RX + kb);
            }
            #pragma unroll
            for (int mt = 0; mt < 4; mt++) {  // A: 64 rows = 4 x 16-row blocks
                const uint32_t row = (uint32_t)(warp_m * 64 + mt * 16) + lm_row;
                ldmatrix_x4(afr[mt], a_s + row * K6_RX + kb);
            }
            #pragma unroll
            for (int mt = 0; mt < 4; mt++)
                #pragma unroll
                for (int nt = 0; nt < 8; nt++)
                    mma_fp16(acc[mt][nt], afr[mt],
                             bfr[nt >> 1][nt & 1], bfr[nt >> 1][(nt & 1) + 2]);
        }
    }

    // -------- fused fuzzy epilogue (writes fp16 F) --------
    // Warp owns cols [n0 + warp_n*64, +64) = 4 output features (g = 0..3),
    // all within one head (n0 aligned to 128 -> hd block of 8, head-aligned).
    const int q   = lane & 3;
    const int rg  = lane >> 2;
    const int hd0 = n0 >> 4;
    const int h   = hd0 >> 6;
    const int d0c = hd0 & 63;

    float bvv[4][4];   // [g][ntl*2+j]
    #pragma unroll
    for (int g = 0; g < 4; g++)
        #pragma unroll
        for (int ntl = 0; ntl < 2; ntl++)
            #pragma unroll
            for (int j = 0; j < 2; j++)
                bvv[g][ntl * 2 + j] =
                    __ldg(bv + n0 + warp_n * 64 + g * 16 + ntl * 8 + q * 2 + j);

    #pragma unroll
    for (int mt = 0; mt < 4; mt++) {
        #pragma unroll
        for (int half = 0; half < 2; half++) {
            const int rowm  = warp_m * 64 + mt * 16 + rg + half * 8;
            const int token = m0 + rowm;
            const int b     = token >> 11;
            const int s     = token & 2047;
            const float* ap = g_attn + (size_t)token * (HNUM * RNUM) + h * RNUM;
            const float at0 = ap[q * 2],     at1 = ap[q * 2 + 1];
            const float at2 = ap[q * 2 + 8], at3 = ap[q * 2 + 9];

            // (b,h,s,d) flattened to [8192 x 512]
            const int frow  = (b * HNUM + h) * 256 + (s >> 3);
            const int cbase = (s & 7) * 64;

            #pragma unroll
            for (int g = 0; g < 4; g++) {
                float p = (acc[mt][g * 2 + 0][half * 2 + 0] + bvv[g][0]) * at0
                        + (acc[mt][g * 2 + 0][half * 2 + 1] + bvv[g][1]) * at1
                        + (acc[mt][g * 2 + 1][half * 2 + 0] + bvv[g][2]) * at2
                        + (acc[mt][g * 2 + 1][half * 2 + 1] + bvv[g][3]) * at3;
                p += __shfl_down_sync(0xffffffffu, p, 2);
                p += __shfl_down_sync(0xffffffffu, p, 1);
                if (q == 0) {
                    p *= 0.125f;  // D^-0.5
                    const int col = cbase + d0c + warp_n * 4 + g;
                    g_Fh[(size_t)frow * EDIM + col] = __float2half_rn(p);
                }
            }
        }
    }
}

// ---------------------------------------------------------------------------
extern "C" void kernel_launch(void* const* d_in, const int* in_sizes, int n_in,
                              void* d_out, int out_size)
{
    const float* query = (const float*)d_in[0];
    // d_in[1] = key: unused by the reference computation
    const float* value = (const float*)d_in[2];
    const float* Wq    = (const float*)d_in[3];
    const float* bq    = (const float*)d_in[4];
    const float* Wv    = (const float*)d_in[5];
    const float* bv    = (const float*)d_in[6];
    const float* Wo    = (const float*)d_in[7];
    const float* bo    = (const float*)d_in[8];
    const float* rk    = (const float*)d_in[9];
    const float* rw    = (const float*)d_in[10];
    float* out = (float*)d_out;

    float* Qp = nullptr;
    __half *Qh = nullptr, *Wqh = nullptr, *Woh = nullptr, *Fh = nullptr;
    cudaGetSymbolAddress((void**)&Qp,  g_Q);
    cudaGetSymbolAddress((void**)&Qh,  g_Qh);
    cudaGetSymbolAddress((void**)&Wqh, g_Wqh);
    cudaGetSymbolAddress((void**)&Woh, g_Woh);
    cudaGetSymbolAddress((void**)&Fh,  g_Fh);

    cudaFuncSetAttribute(hmma_fused_v6_kernel,
                         cudaFuncAttributeMaxDynamicSharedMemorySize, K6_SMEM);

    dim3 blk(256);

    // 1-2: merged fp32 -> fp16 conversions
    convA_kernel<<<dim3((2 * N4_TOK) / 256), blk>>>(value, query);
    convB_kernel<<<dim3((N4_WV + 2 * N4_W) / 256), blk>>>(Wv, Wq, Wo);
    // 3: rule width preprocessing
    prep_iw2_kernel<<<dim3((HNUM * RNUM * DDIM + 255) / 256), blk>>>(rw);

    // 4: K1 q projection (scaled)
    hmma_gemm16_kernel<<<dim3(EDIM / 128, TOK / 128), blk>>>(
        Qh, Wqh, bq, Qp, 0.125f);

    // 5: K2 fuzzy rule attention
    attn_kernel<<<dim3(TOK), blk>>>(rk);

    // 6: K3 fused v-GEMM + rule reduction (64x64 warp tiles)
    hmma_fused_v6_kernel<<<dim3(ERDIM / 128, TOK / 128), dim3(128), K6_SMEM>>>(bv);

    // 7: K4 output projection (reads g_Fh directly)
    hmma_gemm16_kernel<<<dim3(EDIM / 128, TOK / 128), blk>>>(
        Fh, Woh, bo, out, 1.0f);
}